// round 2
// baseline (speedup 1.0000x reference)
#include <cuda_runtime.h>

// Problem dims
#define BB    32
#define NNODE 512
#define FIN   256
#define HID   512
#define OUTC  512
#define NHEAD 4
#define DH    128
#define EPSV  1e-5f

// Scratch (device globals: allocation-free)
__device__ float g_support[(size_t)BB * NNODE * HID];            // 32 MB
__device__ float g_gact[(size_t)BB * NNODE * HID];               // 32 MB
__device__ float g_hh[(size_t)BB * NNODE * OUTC];                // 32 MB  [b][n][h*DH+d]
__device__ float g_att[(size_t)BB * NHEAD * NNODE * NNODE];      // 128 MB [b][h][q][k]
__device__ float g_o[(size_t)BB * NNODE * OUTC];                 // 32 MB  [b][n][h*DH+d]

// ---------------------------------------------------------------------------
// Generic 128x128x8 SGEMM, 256 threads, 8x8 per thread.
// BT: B is [Nc,K] row-major (use B^T).  EPI: 0 none, 1 bias+BN+ReLU, 2 LeakyReLU.
// blockIdx.z decomposed as z1 = z/zdiv, z2 = z%zdiv with independent strides
// (covers batched and batched-per-head cases).
// ---------------------------------------------------------------------------
template <bool BT, int EPI>
__global__ __launch_bounds__(256, 2) void gemm_k(
    const float* __restrict__ A, int lda, long sA1, long sA2,
    const float* __restrict__ B, int ldb, long sB1, long sB2,
    float* __restrict__ C, int ldc, long sC1, long sC2,
    int K, int zdiv,
    const float* __restrict__ bias,
    const float* __restrict__ bng, const float* __restrict__ bnb,
    const float* __restrict__ bnm, const float* __restrict__ bnv)
{
    const int z  = blockIdx.z;
    const int z1 = z / zdiv;
    const int z2 = z - z1 * zdiv;
    A += (long)z1 * sA1 + (long)z2 * sA2;
    B += (long)z1 * sB1 + (long)z2 * sB2;
    C += (long)z1 * sC1 + (long)z2 * sC2;

    const int m0 = blockIdx.y * 128;
    const int n0 = blockIdx.x * 128;

    __shared__ float As[8][128];
    __shared__ float Bs[8][128];

    const int t   = threadIdx.x;
    const int tx  = t & 15;
    const int ty  = t >> 4;
    const int am  = t >> 1;         // 0..127 (tile row for A / B^T loads)
    const int ak4 = (t & 1) * 4;    // 0 or 4
    const int kb  = t >> 5;         // 0..7   (NN B load)
    const int nb4 = (t & 31) * 4;   // 0..124

    float acc[8][8];
#pragma unroll
    for (int i = 0; i < 8; i++)
#pragma unroll
        for (int j = 0; j < 8; j++) acc[i][j] = 0.f;

    for (int k0 = 0; k0 < K; k0 += 8) {
        float4 a4 = *reinterpret_cast<const float4*>(A + (long)(m0 + am) * lda + k0 + ak4);
        As[ak4 + 0][am] = a4.x; As[ak4 + 1][am] = a4.y;
        As[ak4 + 2][am] = a4.z; As[ak4 + 3][am] = a4.w;
        if (BT) {
            float4 b4 = *reinterpret_cast<const float4*>(B + (long)(n0 + am) * ldb + k0 + ak4);
            Bs[ak4 + 0][am] = b4.x; Bs[ak4 + 1][am] = b4.y;
            Bs[ak4 + 2][am] = b4.z; Bs[ak4 + 3][am] = b4.w;
        } else {
            float4 b4 = *reinterpret_cast<const float4*>(B + (long)(k0 + kb) * ldb + n0 + nb4);
            *reinterpret_cast<float4*>(&Bs[kb][nb4]) = b4;
        }
        __syncthreads();
#pragma unroll
        for (int kk = 0; kk < 8; kk++) {
            float4 a0 = *reinterpret_cast<const float4*>(&As[kk][ty * 4]);
            float4 a1 = *reinterpret_cast<const float4*>(&As[kk][64 + ty * 4]);
            float4 b0 = *reinterpret_cast<const float4*>(&Bs[kk][tx * 4]);
            float4 b1 = *reinterpret_cast<const float4*>(&Bs[kk][64 + tx * 4]);
            float ar[8] = {a0.x, a0.y, a0.z, a0.w, a1.x, a1.y, a1.z, a1.w};
            float br[8] = {b0.x, b0.y, b0.z, b0.w, b1.x, b1.y, b1.z, b1.w};
#pragma unroll
            for (int i = 0; i < 8; i++)
#pragma unroll
                for (int j = 0; j < 8; j++) acc[i][j] = fmaf(ar[i], br[j], acc[i][j]);
        }
        __syncthreads();
    }

#pragma unroll
    for (int i = 0; i < 8; i++) {
        const int m = m0 + ((i < 4) ? (ty * 4 + i) : (64 + ty * 4 + (i - 4)));
#pragma unroll
        for (int j = 0; j < 8; j++) {
            const int n = n0 + ((j < 4) ? (tx * 4 + j) : (64 + tx * 4 + (j - 4)));
            float v = acc[i][j];
            if (EPI == 1) {
                float s = bng[n] * rsqrtf(bnv[n] + EPSV);
                v = (v + bias[n] - bnm[n]) * s + bnb[n];
                v = fmaxf(v, 0.f);
            } else if (EPI == 2) {
                v = (v > 0.f) ? v : 0.2f * v;
            }
            C[(long)m * ldc + n] = v;
        }
    }
}

// ---------------------------------------------------------------------------
// Row softmax over 512 contiguous floats. One block per row, 256 threads.
// ---------------------------------------------------------------------------
__global__ void softmax512(float* __restrict__ att)
{
    __shared__ float red[256];
    const long row = blockIdx.x;
    float* p = att + row * 512;
    const int t = threadIdx.x;
    float a = p[t];
    float b = p[t + 256];
    red[t] = fmaxf(a, b);
    __syncthreads();
    for (int s = 128; s > 0; s >>= 1) {
        if (t < s) red[t] = fmaxf(red[t], red[t + s]);
        __syncthreads();
    }
    const float m = red[0];
    __syncthreads();
    float e0 = __expf(a - m);
    float e1 = __expf(b - m);
    red[t] = e0 + e1;
    __syncthreads();
    for (int s = 128; s > 0; s >>= 1) {
        if (t < s) red[t] += red[t + s];
        __syncthreads();
    }
    const float inv = 1.f / red[0];
    p[t]       = e0 * inv;
    p[t + 256] = e1 * inv;
}

// ---------------------------------------------------------------------------
// conv1d(k=3, pad=1) over node axis + bias + BN2(eval) + ReLU.
// out[b,n,co] = relu(bn2(sum_{k,ci} o[b, n+k-1, ci] * w[co,ci,k] + cb[co]))
// GEMM-shaped: 128x128 tile, K loop = 3 shifts x (512/8) ci-tiles.
// ---------------------------------------------------------------------------
__global__ __launch_bounds__(256, 2) void conv_bn_k(
    const float* __restrict__ o, const float* __restrict__ w,
    const float* __restrict__ cb,
    const float* __restrict__ bng, const float* __restrict__ bnb,
    const float* __restrict__ bnm, const float* __restrict__ bnv,
    float* __restrict__ out)
{
    const int b   = blockIdx.z;
    const int n0  = blockIdx.y * 128;
    const int co0 = blockIdx.x * 128;

    __shared__ float As[8][128];
    __shared__ float Bs[8][128];

    const int t   = threadIdx.x;
    const int tx  = t & 15;
    const int ty  = t >> 4;
    const int am  = t >> 1;
    const int ak4 = (t & 1) * 4;

    float acc[8][8];
#pragma unroll
    for (int i = 0; i < 8; i++)
#pragma unroll
        for (int j = 0; j < 8; j++) acc[i][j] = 0.f;

    const float* ob = o + (long)b * NNODE * OUTC;

    for (int k = 0; k < 3; k++) {
        const int r = n0 + am + k - 1;
        const bool valid = (r >= 0) && (r < NNODE);
        for (int ci0 = 0; ci0 < OUTC; ci0 += 8) {
            float4 a4 = make_float4(0.f, 0.f, 0.f, 0.f);
            if (valid) a4 = *reinterpret_cast<const float4*>(ob + (long)r * OUTC + ci0 + ak4);
            As[ak4 + 0][am] = a4.x; As[ak4 + 1][am] = a4.y;
            As[ak4 + 2][am] = a4.z; As[ak4 + 3][am] = a4.w;
#pragma unroll
            for (int j = 0; j < 4; j++)
                Bs[ak4 + j][am] =
                    w[(long)(co0 + am) * (OUTC * 3) + (long)(ci0 + ak4 + j) * 3 + k];
            __syncthreads();
#pragma unroll
            for (int kk = 0; kk < 8; kk++) {
                float4 a0 = *reinterpret_cast<const float4*>(&As[kk][ty * 4]);
                float4 a1 = *reinterpret_cast<const float4*>(&As[kk][64 + ty * 4]);
                float4 b0 = *reinterpret_cast<const float4*>(&Bs[kk][tx * 4]);
                float4 b1 = *reinterpret_cast<const float4*>(&Bs[kk][64 + tx * 4]);
                float ar[8] = {a0.x, a0.y, a0.z, a0.w, a1.x, a1.y, a1.z, a1.w};
                float br[8] = {b0.x, b0.y, b0.z, b0.w, b1.x, b1.y, b1.z, b1.w};
#pragma unroll
                for (int i = 0; i < 8; i++)
#pragma unroll
                    for (int j = 0; j < 8; j++) acc[i][j] = fmaf(ar[i], br[j], acc[i][j]);
            }
            __syncthreads();
        }
    }

#pragma unroll
    for (int i = 0; i < 8; i++) {
        const int n = n0 + ((i < 4) ? (ty * 4 + i) : (64 + ty * 4 + (i - 4)));
#pragma unroll
        for (int j = 0; j < 8; j++) {
            const int co = co0 + ((j < 4) ? (tx * 4 + j) : (64 + tx * 4 + (j - 4)));
            float s = bng[co] * rsqrtf(bnv[co] + EPSV);
            float v = (acc[i][j] + cb[co] - bnm[co]) * s + bnb[co];
            v = fmaxf(v, 0.f);
            out[(long)b * NNODE * OUTC + (long)n * OUTC + co] = v;
        }
    }
}

// ---------------------------------------------------------------------------
extern "C" void kernel_launch(void* const* d_in, const int* in_sizes, int n_in,
                              void* d_out, int out_size)
{
    const float* x      = (const float*)d_in[0];
    const float* adj    = (const float*)d_in[1];
    const float* gc_w   = (const float*)d_in[2];
    const float* gc_b   = (const float*)d_in[3];
    const float* bn1g   = (const float*)d_in[4];
    const float* bn1b   = (const float*)d_in[5];
    const float* bn1m   = (const float*)d_in[6];
    const float* bn1v   = (const float*)d_in[7];
    const float* gat_w  = (const float*)d_in[8];
    const float* conv_w = (const float*)d_in[9];
    const float* conv_b = (const float*)d_in[10];
    const float* bn2g   = (const float*)d_in[11];
    const float* bn2b   = (const float*)d_in[12];
    const float* bn2m   = (const float*)d_in[13];
    const float* bn2v   = (const float*)d_in[14];
    float* out = (float*)d_out;

    float *sup, *g, *hh, *att, *o;
    cudaGetSymbolAddress((void**)&sup, g_support);
    cudaGetSymbolAddress((void**)&g,   g_gact);
    cudaGetSymbolAddress((void**)&hh,  g_hh);
    cudaGetSymbolAddress((void**)&att, g_att);
    cudaGetSymbolAddress((void**)&o,   g_o);

    const long sNH = (long)NNODE * HID;    // 262144
    const long sNO = (long)NNODE * OUTC;   // 262144
    const long sBH = (long)NHEAD * NNODE * NNODE;  // 1048576
    const long sNN = (long)NNODE * NNODE;  // 262144

    // 1) support = x @ gc_w                    [B*N,FIN]@[FIN,HID]
    gemm_k<false, 0><<<dim3(HID / 128, (BB * NNODE) / 128, 1), 256>>>(
        x, FIN, 0, 0, gc_w, HID, 0, 0, sup, HID, 0, 0, FIN, 1,
        nullptr, nullptr, nullptr, nullptr, nullptr);

    // 2) g = relu(bn1(adj @ support + gc_b))   per batch
    gemm_k<false, 1><<<dim3(HID / 128, NNODE / 128, BB), 256>>>(
        adj, NNODE, 0, 0, sup, HID, sNH, 0, g, HID, sNH, 0, NNODE, 1,
        gc_b, bn1g, bn1b, bn1m, bn1v);

    // 3) hh = g @ gat_w^T                      per batch, W=[512,512] row-major
    gemm_k<true, 0><<<dim3(OUTC / 128, NNODE / 128, BB), 256>>>(
        g, HID, sNH, 0, gat_w, HID, 0, 0, hh, OUTC, sNO, 0, HID, 1,
        nullptr, nullptr, nullptr, nullptr, nullptr);

    // 4) att logits = leaky(hh_h @ hh_h^T)     per (b,h)
    gemm_k<true, 2><<<dim3(NNODE / 128, NNODE / 128, BB * NHEAD), 256>>>(
        hh, OUTC, sNO, DH, hh, OUTC, sNO, DH,
        att, NNODE, sBH, sNN, DH, NHEAD,
        nullptr, nullptr, nullptr, nullptr, nullptr);

    // 5) row softmax
    softmax512<<<BB * NHEAD * NNODE, 256>>>(att);

    // 6) o = att @ hh_h                        per (b,h)
    gemm_k<false, 0><<<dim3(DH / 128, NNODE / 128, BB * NHEAD), 256>>>(
        att, NNODE, sBH, sNN, hh, OUTC, sNO, DH,
        o, OUTC, sNO, DH, NNODE, NHEAD,
        nullptr, nullptr, nullptr, nullptr, nullptr);

    // 7) conv1d + bias + bn2 + relu -> out [B,N,OUT]
    conv_bn_k<<<dim3(OUTC / 128, NNODE / 128, BB), 256>>>(
        o, conv_w, conv_b, bn2g, bn2b, bn2m, bn2v, out);
}

// round 5
// speedup vs baseline: 1.2814x; 1.2814x over previous
#include <cuda_runtime.h>
#include <cuda_bf16.h>
#include <cstdint>

// Problem dims
#define BB    32
#define NNODE 512
#define FIN   256
#define HID   512
#define OUTC  512
#define NHEAD 4
#define DH    128
#define EPSV  1e-5f

#define KC    32          // k-chunk (bf16 halves) per smem stage
#define SP    40          // padded plane stride in halves (20 words, %32==20 -> frag-LDS conflict-free)

// Scratch (device globals: allocation-free)
__device__ float g_support[(size_t)BB * NNODE * HID];
__device__ float g_gact[(size_t)BB * NNODE * HID];
__device__ float g_hh[(size_t)BB * NNODE * OUTC];
__device__ float g_att[(size_t)BB * NHEAD * NNODE * NNODE];
__device__ float g_o[(size_t)BB * NNODE * OUTC];

__device__ __forceinline__ void mma16816(float* c, const uint32_t* a, const uint32_t* b) {
    asm volatile(
        "mma.sync.aligned.m16n8k16.row.col.f32.bf16.bf16.f32 "
        "{%0,%1,%2,%3}, {%4,%5,%6,%7}, {%8,%9}, {%0,%1,%2,%3};"
        : "+f"(c[0]), "+f"(c[1]), "+f"(c[2]), "+f"(c[3])
        : "r"(a[0]), "r"(a[1]), "r"(a[2]), "r"(a[3]), "r"(b[0]), "r"(b[1]));
}

// split x -> (hi, lo) bf16
__device__ __forceinline__ void split_bf16(float x, __nv_bfloat16& h, __nv_bfloat16& l) {
    h = __float2bfloat16_rn(x);
    l = __float2bfloat16_rn(x - __bfloat162float(h));
}

// ---------------------------------------------------------------------------
// bf16x3 GEMM: C[128,128] tile = A @ B^T (+epilogue), 256 threads, 8 warps 4x2.
// BMODE: 0 = B rows K-major direct ([n][k] source)
//        1 = B staged transpose (source [K, N] row-major)
//        2 = conv weights w[co, ci, kpos] (gather stride 3)
// CONV:  A rows shifted by (kpos-1), zero-padded; 48 K-steps (3 x 16).
// EPI:   0 none, 1 (v+bias-m)*s+b then ReLU, 2 LeakyReLU(0.2)
// ---------------------------------------------------------------------------
template <int BMODE, int EPI, bool CONV>
__global__ void __launch_bounds__(256) tc_gemm(
    const float* __restrict__ A, int lda, long sA1, long sA2,
    const float* __restrict__ Bsrc, int ldb, long sB1, long sB2,
    float* __restrict__ C, int ldc, long sC1, long sC2,
    int K, int zdiv,
    const float* __restrict__ bias,
    const float* __restrict__ bng, const float* __restrict__ bnb,
    const float* __restrict__ bnm, const float* __restrict__ bnv)
{
    __shared__ __align__(16) __nv_bfloat16 Ah[128][SP];
    __shared__ __align__(16) __nv_bfloat16 Al[128][SP];
    __shared__ __align__(16) __nv_bfloat16 Bh[128][SP];
    __shared__ __align__(16) __nv_bfloat16 Bl[128][SP];

    const int z  = blockIdx.z;
    const int z1 = z / zdiv;
    const int z2 = z - z1 * zdiv;
    A    += (long)z1 * sA1 + (long)z2 * sA2;
    Bsrc += (long)z1 * sB1 + (long)z2 * sB2;
    C    += (long)z1 * sC1 + (long)z2 * sC2;

    const int m0 = blockIdx.y * 128;
    const int n0 = blockIdx.x * 128;
    const int tid = threadIdx.x;

    const int w    = tid >> 5;
    const int lane = tid & 31;
    const int gq   = lane >> 2;      // 0..7
    const int tig  = lane & 3;       // 0..3
    const int wm   = (w >> 1) * 32;  // warp m offset (4 warps)
    const int wn   = (w & 1) * 64;   // warp n offset (2 warps)

    // staging indices
    const int ar  = tid >> 1;         // 0..127
    const int ac0 = (tid & 1) * 16;   // 0 or 16 (k-halves base)
    const int bkk = tid >> 3;         // 0..31  (transpose: k col)
    const int ba  = tid & 7;          // transpose: n block 0..7
    const int bj0 = ba * 16;

    float acc[2][8][4];
#pragma unroll
    for (int i = 0; i < 2; i++)
#pragma unroll
        for (int j = 0; j < 8; j++)
#pragma unroll
            for (int q = 0; q < 4; q++) acc[i][j][q] = 0.f;

    const int steps = CONV ? 48 : (K >> 5);

    for (int s = 0; s < steps; s++) {
        int k0, shift;
        if (CONV) { shift = s >> 4; k0 = (s & 15) * KC; }
        else      { shift = 0;      k0 = s * KC; }

        // ---- stage A tile (rows m, k contiguous), split into hi/lo planes ----
        {
            bool valid = true;
            long row = m0 + ar;
            if (CONV) {
                int rs = m0 + ar + shift - 1;
                valid = (rs >= 0) && (rs < NNODE);
                row = rs;
            }
            const float4* ap = reinterpret_cast<const float4*>(A + row * lda + k0 + ac0);
#pragma unroll
            for (int j = 0; j < 4; j++) {
                float4 v = valid ? ap[j] : make_float4(0.f, 0.f, 0.f, 0.f);
                const float vv[4] = {v.x, v.y, v.z, v.w};
#pragma unroll
                for (int q = 0; q < 4; q++) {
                    __nv_bfloat16 h, l;
                    split_bf16(vv[q], h, l);
                    Ah[ar][ac0 + 4 * j + q] = h;
                    Al[ar][ac0 + 4 * j + q] = l;
                }
            }
        }
        // ---- stage B tile (rows n, k contiguous) ----
        if (BMODE == 0) {
            const float4* bp = reinterpret_cast<const float4*>(Bsrc + (long)(n0 + ar) * ldb + k0 + ac0);
#pragma unroll
            for (int j = 0; j < 4; j++) {
                float4 v = bp[j];
                const float vv[4] = {v.x, v.y, v.z, v.w};
#pragma unroll
                for (int q = 0; q < 4; q++) {
                    __nv_bfloat16 h, l;
                    split_bf16(vv[q], h, l);
                    Bh[ar][ac0 + 4 * j + q] = h;
                    Bl[ar][ac0 + 4 * j + q] = l;
                }
            }
        } else if (BMODE == 1) {
            // coalesced load of 16 n-contiguous floats at k-row bkk
            float vbuf[16];
            const float4* bp = reinterpret_cast<const float4*>(Bsrc + (long)(k0 + bkk) * ldb + n0 + bj0);
#pragma unroll
            for (int q = 0; q < 4; q++) {
                float4 v = bp[q];
                vbuf[4 * q + 0] = v.x; vbuf[4 * q + 1] = v.y;
                vbuf[4 * q + 2] = v.z; vbuf[4 * q + 3] = v.w;
            }
            // rotated scatter: row = bj0 + ((j + ba) & 15) -> conflict-reduced
#pragma unroll
            for (int j = 0; j < 16; j++) {
                const int idx = (j + ba) & 15;
                __nv_bfloat16 h, l;
                split_bf16(vbuf[idx], h, l);
                Bh[bj0 + idx][bkk] = h;
                Bl[bj0 + idx][bkk] = l;
            }
        } else {  // conv weights: Bsrc[co][ci][kpos], stride-3 gather
#pragma unroll
            for (int j = 0; j < 16; j++) {
                int ci = k0 + ac0 + j;
                float v = Bsrc[(long)(n0 + ar) * (OUTC * 3) + (long)ci * 3 + shift];
                __nv_bfloat16 h, l;
                split_bf16(v, h, l);
                Bh[ar][ac0 + j] = h;
                Bl[ar][ac0 + j] = l;
            }
        }
        __syncthreads();

        // ---- compute: 2 substeps of k16; 3 bf16 passes (hh, hl, lh) each ----
#pragma unroll
        for (int ks = 0; ks < KC; ks += 16) {
            uint32_t afh[2][4], afl[2][4];
#pragma unroll
            for (int mt = 0; mt < 2; mt++) {
                const int r = wm + mt * 16 + gq;
                afh[mt][0] = *reinterpret_cast<const uint32_t*>(&Ah[r    ][ks + 2 * tig]);
                afh[mt][1] = *reinterpret_cast<const uint32_t*>(&Ah[r + 8][ks + 2 * tig]);
                afh[mt][2] = *reinterpret_cast<const uint32_t*>(&Ah[r    ][ks + 2 * tig + 8]);
                afh[mt][3] = *reinterpret_cast<const uint32_t*>(&Ah[r + 8][ks + 2 * tig + 8]);
                afl[mt][0] = *reinterpret_cast<const uint32_t*>(&Al[r    ][ks + 2 * tig]);
                afl[mt][1] = *reinterpret_cast<const uint32_t*>(&Al[r + 8][ks + 2 * tig]);
                afl[mt][2] = *reinterpret_cast<const uint32_t*>(&Al[r    ][ks + 2 * tig + 8]);
                afl[mt][3] = *reinterpret_cast<const uint32_t*>(&Al[r + 8][ks + 2 * tig + 8]);
            }
#pragma unroll
            for (int nt = 0; nt < 8; nt++) {
                const int c = wn + nt * 8 + gq;
                uint32_t bfh[2], bfl[2];
                bfh[0] = *reinterpret_cast<const uint32_t*>(&Bh[c][ks + 2 * tig]);
                bfh[1] = *reinterpret_cast<const uint32_t*>(&Bh[c][ks + 2 * tig + 8]);
                bfl[0] = *reinterpret_cast<const uint32_t*>(&Bl[c][ks + 2 * tig]);
                bfl[1] = *reinterpret_cast<const uint32_t*>(&Bl[c][ks + 2 * tig + 8]);
#pragma unroll
                for (int mt = 0; mt < 2; mt++) {
                    mma16816(acc[mt][nt], afh[mt], bfh);
                    mma16816(acc[mt][nt], afh[mt], bfl);
                    mma16816(acc[mt][nt], afl[mt], bfh);
                }
            }
        }
        __syncthreads();
    }

    // ---- epilogue: c0,c1 -> (row g, cols 2tig,2tig+1); c2,c3 -> row g+8 ----
#pragma unroll
    for (int mt = 0; mt < 2; mt++) {
        const long r0 = m0 + wm + mt * 16 + gq;
        const long r1 = r0 + 8;
#pragma unroll
        for (int nt = 0; nt < 8; nt++) {
            const int cb = n0 + wn + nt * 8 + 2 * tig;
            float v[4] = {acc[mt][nt][0], acc[mt][nt][1], acc[mt][nt][2], acc[mt][nt][3]};
            if (EPI == 1) {
#pragma unroll
                for (int q = 0; q < 4; q++) {
                    const int n = cb + (q & 1);
                    float sc = bng[n] * rsqrtf(bnv[n] + EPSV);
                    v[q] = (v[q] + bias[n] - bnm[n]) * sc + bnb[n];
                    v[q] = fmaxf(v[q], 0.f);
                }
            } else if (EPI == 2) {
#pragma unroll
                for (int q = 0; q < 4; q++) v[q] = (v[q] > 0.f) ? v[q] : 0.2f * v[q];
            }
            *reinterpret_cast<float2*>(C + r0 * ldc + cb) = make_float2(v[0], v[1]);
            *reinterpret_cast<float2*>(C + r1 * ldc + cb) = make_float2(v[2], v[3]);
        }
    }
}

// ---------------------------------------------------------------------------
// Row softmax over 512 contiguous floats. One block per row, 256 threads.
// ---------------------------------------------------------------------------
__global__ void softmax512(float* __restrict__ att)
{
    __shared__ float red[256];
    const long row = blockIdx.x;
    float* p = att + row * 512;
    const int t = threadIdx.x;
    float a = p[t];
    float b = p[t + 256];
    red[t] = fmaxf(a, b);
    __syncthreads();
    for (int s = 128; s > 0; s >>= 1) {
        if (t < s) red[t] = fmaxf(red[t], red[t + s]);
        __syncthreads();
    }
    const float m = red[0];
    __syncthreads();
    float e0 = __expf(a - m);
    float e1 = __expf(b - m);
    red[t] = e0 + e1;
    __syncthreads();
    for (int s = 128; s > 0; s >>= 1) {
        if (t < s) red[t] += red[t + s];
        __syncthreads();
    }
    const float inv = 1.f / red[0];
    p[t]       = e0 * inv;
    p[t + 256] = e1 * inv;
}

// ---------------------------------------------------------------------------
extern "C" void kernel_launch(void* const* d_in, const int* in_sizes, int n_in,
                              void* d_out, int out_size)
{
    const float* x      = (const float*)d_in[0];
    const float* adj    = (const float*)d_in[1];
    const float* gc_w   = (const float*)d_in[2];
    const float* gc_b   = (const float*)d_in[3];
    const float* bn1g   = (const float*)d_in[4];
    const float* bn1b   = (const float*)d_in[5];
    const float* bn1m   = (const float*)d_in[6];
    const float* bn1v   = (const float*)d_in[7];
    const float* gat_w  = (const float*)d_in[8];
    const float* conv_w = (const float*)d_in[9];
    const float* conv_b = (const float*)d_in[10];
    const float* bn2g   = (const float*)d_in[11];
    const float* bn2b   = (const float*)d_in[12];
    const float* bn2m   = (const float*)d_in[13];
    const float* bn2v   = (const float*)d_in[14];
    float* out = (float*)d_out;

    float *sup, *g, *hh, *att, *o;
    cudaGetSymbolAddress((void**)&sup, g_support);
    cudaGetSymbolAddress((void**)&g,   g_gact);
    cudaGetSymbolAddress((void**)&hh,  g_hh);
    cudaGetSymbolAddress((void**)&att, g_att);
    cudaGetSymbolAddress((void**)&o,   g_o);

    const long sNH = (long)NNODE * HID;            // 262144
    const long sNO = (long)NNODE * OUTC;           // 262144
    const long sBH = (long)NHEAD * NNODE * NNODE;  // 1048576
    const long sNN = (long)NNODE * NNODE;          // 262144

    // 1) support = x @ gc_w            [16384,256]@[256,512]   (B staged)
    tc_gemm<1, 0, false><<<dim3(4, 128, 1), 256>>>(
        x, FIN, 0, 0, gc_w, HID, 0, 0, sup, HID, 0, 0, FIN, 1,
        nullptr, nullptr, nullptr, nullptr, nullptr);

    // 2) g = relu(bn1(adj @ support + gc_b))   per batch        (B staged)
    tc_gemm<1, 1, false><<<dim3(4, 4, BB), 256>>>(
        adj, NNODE, 0, 0, sup, HID, sNH, 0, g, HID, sNH, 0, NNODE, 1,
        gc_b, bn1g, bn1b, bn1m, bn1v);

    // 3) hh = g @ gat_w^T              per batch                (B direct)
    tc_gemm<0, 0, false><<<dim3(4, 4, BB), 256>>>(
        g, HID, sNH, 0, gat_w, HID, 0, 0, hh, OUTC, sNO, 0, HID, 1,
        nullptr, nullptr, nullptr, nullptr, nullptr);

    // 4) logits = leaky(hh_h @ hh_h^T) per (b,h)                (B direct)
    tc_gemm<0, 2, false><<<dim3(4, 4, BB * NHEAD), 256>>>(
        hh, OUTC, sNO, DH, hh, OUTC, sNO, DH,
        att, NNODE, sBH, sNN, DH, NHEAD,
        nullptr, nullptr, nullptr, nullptr, nullptr);

    // 5) row softmax
    softmax512<<<BB * NHEAD * NNODE, 256>>>(att);

    // 6) o = att @ hh_h                per (b,h)                (B staged)
    tc_gemm<1, 0, false><<<dim3(1, 4, BB * NHEAD), 256>>>(
        att, NNODE, sBH, sNN, hh, OUTC, sNO, DH,
        o, OUTC, sNO, DH, NNODE, NHEAD,
        nullptr, nullptr, nullptr, nullptr, nullptr);

    // 7) conv1d(k=3,p=1) + bias + bn2 + relu -> out [B,N,OUT]
    tc_gemm<2, 1, true><<<dim3(4, 4, BB), 256>>>(
        o, OUTC, sNO, 0, conv_w, 0, 0, 0, out, OUTC, (long)NNODE * OUTC, 0,
        3 * OUTC, 1,
        conv_b, bn2g, bn2b, bn2m, bn2v);
}

// round 6
// speedup vs baseline: 1.6717x; 1.3046x over previous
#include <cuda_runtime.h>
#include <cuda_bf16.h>
#include <cstdint>

// Problem dims
#define BB    32
#define NNODE 512
#define FIN   256
#define HID   512
#define OUTC  512
#define NHEAD 4
#define DH    128
#define EPSV  1e-5f

#define KC    32          // k-chunk (elements) per smem stage

// Scratch (device globals: allocation-free)
__device__ float g_support[(size_t)BB * NNODE * HID];
__device__ float g_gact[(size_t)BB * NNODE * HID];
__device__ float g_hh[(size_t)BB * NNODE * OUTC];
__device__ float g_att[(size_t)BB * NHEAD * NNODE * NNODE];
__device__ float g_o[(size_t)BB * NNODE * OUTC];

__device__ __forceinline__ void mma16816(float* c, const uint32_t* a, const uint32_t* b) {
    asm volatile(
        "mma.sync.aligned.m16n8k16.row.col.f32.bf16.bf16.f32 "
        "{%0,%1,%2,%3}, {%4,%5,%6,%7}, {%8,%9}, {%0,%1,%2,%3};"
        : "+f"(c[0]), "+f"(c[1]), "+f"(c[2]), "+f"(c[3])
        : "r"(a[0]), "r"(a[1]), "r"(a[2]), "r"(a[3]), "r"(b[0]), "r"(b[1]));
}

__device__ __forceinline__ void split_bf16(float x, __nv_bfloat16& h, __nv_bfloat16& l) {
    h = __float2bfloat16_rn(x);
    l = __float2bfloat16_rn(x - __bfloat162float(h));
}

// swizzled plane layout: 128 rows x 64B (4 chunks of 8 bf16).
// chunk placed at (chunk ^ ((row>>1)&3)) -> conflict-free for 16B stores and ldmatrix.
__device__ __forceinline__ uint32_t sw_off(int row, int chunk) {
    return (uint32_t)((row << 6) + (((chunk) ^ ((row >> 1) & 3)) << 4));
}

__device__ __forceinline__ void ldm_x4(uint32_t& r0, uint32_t& r1, uint32_t& r2, uint32_t& r3,
                                       uint32_t a) {
    asm volatile("ldmatrix.sync.aligned.m8n8.x4.shared.b16 {%0,%1,%2,%3}, [%4];"
                 : "=r"(r0), "=r"(r1), "=r"(r2), "=r"(r3) : "r"(a));
}

// ---------------------------------------------------------------------------
// bf16x3 GEMM: C[128,128] tile = A @ B^T (+epilogue), 256 threads, 8 warps 4x2.
// BMODE: 0 = B rows K-major direct, 1 = B staged transpose ([K,N] src),
//        2 = conv weights w[co,ci,kpos] (stride-3 gather)
// CONV:  A rows shifted by (kpos-1), zero-padded; 48 K-steps (3 x 16).
// EPI:   0 none, 1 (v+bias-m)*s+b then ReLU, 2 LeakyReLU(0.2)
// ---------------------------------------------------------------------------
template <int BMODE, int EPI, bool CONV>
__global__ void __launch_bounds__(256, 2) tc_gemm(
    const float* __restrict__ A, int lda, long sA1, long sA2,
    const float* __restrict__ Bsrc, int ldb, long sB1, long sB2,
    float* __restrict__ C, int ldc, long sC1, long sC2,
    int K, int zdiv,
    const float* __restrict__ bias,
    const float* __restrict__ bng, const float* __restrict__ bnb,
    const float* __restrict__ bnm, const float* __restrict__ bnv)
{
    __shared__ __align__(16) unsigned char sm[4 * 8192];  // AH | AL | BH | BL planes
    unsigned char* const smp = sm;
    const uint32_t smb = (uint32_t)__cvta_generic_to_shared(sm);
    const uint32_t AHs = smb, ALs = smb + 8192, BHs = smb + 16384, BLs = smb + 24576;

    const int z  = blockIdx.z;
    const int z1 = z / zdiv;
    const int z2 = z - z1 * zdiv;
    A    += (long)z1 * sA1 + (long)z2 * sA2;
    Bsrc += (long)z1 * sB1 + (long)z2 * sB2;
    C    += (long)z1 * sC1 + (long)z2 * sC2;

    const int m0 = blockIdx.y * 128;
    const int n0 = blockIdx.x * 128;
    const int tid = threadIdx.x;

    const int w    = tid >> 5;
    const int lane = tid & 31;
    const int gq   = lane >> 2;
    const int tig  = lane & 3;
    const int wm   = (w >> 1) * 32;  // warp m offset
    const int wn   = (w & 1) * 64;   // warp n offset

    // staging indices
    const int ar  = tid >> 1;         // 0..127 row
    const int ac0 = (tid & 1) * 16;   // k base (chunks ac0/8, ac0/8+1)
    const int bkk = tid >> 3;         // 0..31 (transpose: k col)
    const int ba  = tid & 7;
    const int bj0 = ba * 16;

    float acc[2][8][4];
#pragma unroll
    for (int i = 0; i < 2; i++)
#pragma unroll
        for (int j = 0; j < 8; j++)
#pragma unroll
            for (int q = 0; q < 4; q++) acc[i][j][q] = 0.f;

    const int steps = CONV ? 48 : (K >> 5);

    float av[16], bv[16];

    auto loadA = [&](int s) {
        int k0, shift;
        if (CONV) { shift = s >> 4; k0 = (s & 15) * KC; }
        else      { shift = 0;      k0 = s * KC; }
        bool valid = true;
        long row = m0 + ar;
        if (CONV) {
            int rs = m0 + ar + shift - 1;
            valid = (rs >= 0) && (rs < NNODE);
            row = rs;
        }
        const float4* ap = reinterpret_cast<const float4*>(A + row * lda + k0 + ac0);
#pragma unroll
        for (int j = 0; j < 4; j++) {
            float4 v = valid ? ap[j] : make_float4(0.f, 0.f, 0.f, 0.f);
            av[4 * j + 0] = v.x; av[4 * j + 1] = v.y;
            av[4 * j + 2] = v.z; av[4 * j + 3] = v.w;
        }
    };

    auto loadB = [&](int s) {
        int k0, shift;
        if (CONV) { shift = s >> 4; k0 = (s & 15) * KC; }
        else      { shift = 0;      k0 = s * KC; }
        if (BMODE == 0) {
            const float4* bp = reinterpret_cast<const float4*>(Bsrc + (long)(n0 + ar) * ldb + k0 + ac0);
#pragma unroll
            for (int j = 0; j < 4; j++) {
                float4 v = bp[j];
                bv[4 * j + 0] = v.x; bv[4 * j + 1] = v.y;
                bv[4 * j + 2] = v.z; bv[4 * j + 3] = v.w;
            }
        } else if (BMODE == 1) {
            const float4* bp = reinterpret_cast<const float4*>(Bsrc + (long)(k0 + bkk) * ldb + n0 + bj0);
#pragma unroll
            for (int q = 0; q < 4; q++) {
                float4 v = bp[q];
                bv[4 * q + 0] = v.x; bv[4 * q + 1] = v.y;
                bv[4 * q + 2] = v.z; bv[4 * q + 3] = v.w;
            }
        } else {
#pragma unroll
            for (int j = 0; j < 16; j++) {
                int ci = k0 + ac0 + j;
                bv[j] = Bsrc[(long)(n0 + ar) * (OUTC * 3) + (long)ci * 3 + shift];
            }
        }
    };

    auto stage = [&]() {
        const int c0 = ac0 >> 3;
        // A planes: packed 16B chunk stores
#pragma unroll
        for (int cj = 0; cj < 2; cj++) {
            union { uint4 u; __nv_bfloat16 h[8]; } ph, pl;
#pragma unroll
            for (int q = 0; q < 8; q++) split_bf16(av[cj * 8 + q], ph.h[q], pl.h[q]);
            const uint32_t off = sw_off(ar, c0 + cj);
            *reinterpret_cast<uint4*>(smp + off)        = ph.u;
            *reinterpret_cast<uint4*>(smp + 8192 + off) = pl.u;
        }
        if (BMODE == 0 || BMODE == 2) {
#pragma unroll
            for (int cj = 0; cj < 2; cj++) {
                union { uint4 u; __nv_bfloat16 h[8]; } ph, pl;
#pragma unroll
                for (int q = 0; q < 8; q++) split_bf16(bv[cj * 8 + q], ph.h[q], pl.h[q]);
                const uint32_t off = sw_off(ar, c0 + cj);
                *reinterpret_cast<uint4*>(smp + 16384 + off) = ph.u;
                *reinterpret_cast<uint4*>(smp + 24576 + off) = pl.u;
            }
        } else {
            // transpose scatter with per-lane rotation
            const uint32_t cb = ((uint32_t)(bkk >> 3) << 4) + (uint32_t)(bkk & 7) * 2;
#pragma unroll
            for (int j = 0; j < 16; j++) {
                const int idx = (j + ba) & 15;
                const int row = bj0 + idx;
                __nv_bfloat16 h, l;
                split_bf16(bv[idx], h, l);
                const uint32_t off = (uint32_t)(row << 6)
                    + ((cb & ~15u) ^ (((uint32_t)((row >> 1) & 3)) << 4)) + (cb & 15u);
                *reinterpret_cast<__nv_bfloat16*>(smp + 16384 + off) = h;
                *reinterpret_cast<__nv_bfloat16*>(smp + 24576 + off) = l;
            }
        }
    };

    auto compute = [&]() {
#pragma unroll
        for (int ks = 0; ks < 2; ks++) {
            const int kc = ks * 2;
            uint32_t afh[2][4], afl[2][4];
            const int arow = wm + (lane & 15);
            const int achk = kc + (lane >> 4);
#pragma unroll
            for (int mt = 0; mt < 2; mt++) {
                const uint32_t off = sw_off(arow + mt * 16, achk);
                ldm_x4(afh[mt][0], afh[mt][1], afh[mt][2], afh[mt][3], AHs + off);
                ldm_x4(afl[mt][0], afl[mt][1], afl[mt][2], afl[mt][3], ALs + off);
            }
            const int brow_b = wn + (lane & 7) + ((lane >> 4) << 3);  // +8 for upper half
            const int bchk = kc + ((lane >> 3) & 1);
#pragma unroll
            for (int ntp = 0; ntp < 4; ntp++) {
                const uint32_t off = sw_off(brow_b + ntp * 16, bchk);
                uint32_t bh[4], bl[4];
                ldm_x4(bh[0], bh[1], bh[2], bh[3], BHs + off);
                ldm_x4(bl[0], bl[1], bl[2], bl[3], BLs + off);
#pragma unroll
                for (int hf = 0; hf < 2; hf++) {
                    const int nt = ntp * 2 + hf;
                    uint32_t bfh[2] = {bh[hf * 2], bh[hf * 2 + 1]};
                    uint32_t bfl[2] = {bl[hf * 2], bl[hf * 2 + 1]};
#pragma unroll
                    for (int mt = 0; mt < 2; mt++) {
                        mma16816(acc[mt][nt], afh[mt], bfh);
                        mma16816(acc[mt][nt], afh[mt], bfl);
                        mma16816(acc[mt][nt], afl[mt], bfh);
                    }
                }
            }
        }
    };

    loadA(0); loadB(0);
    for (int s = 0; s < steps; s++) {
        stage();
        __syncthreads();
        if (s + 1 < steps) { loadA(s + 1); loadB(s + 1); }
        compute();
        __syncthreads();
    }

    // ---- epilogue ----
#pragma unroll
    for (int mt = 0; mt < 2; mt++) {
        const long r0 = m0 + wm + mt * 16 + gq;
        const long r1 = r0 + 8;
#pragma unroll
        for (int nt = 0; nt < 8; nt++) {
            const int cb = n0 + wn + nt * 8 + 2 * tig;
            float v[4] = {acc[mt][nt][0], acc[mt][nt][1], acc[mt][nt][2], acc[mt][nt][3]};
            if (EPI == 1) {
#pragma unroll
                for (int q = 0; q < 4; q++) {
                    const int n = cb + (q & 1);
                    float sc = bng[n] * rsqrtf(bnv[n] + EPSV);
                    v[q] = (v[q] + bias[n] - bnm[n]) * sc + bnb[n];
                    v[q] = fmaxf(v[q], 0.f);
                }
            } else if (EPI == 2) {
#pragma unroll
                for (int q = 0; q < 4; q++) v[q] = (v[q] > 0.f) ? v[q] : 0.2f * v[q];
            }
            *reinterpret_cast<float2*>(C + r0 * ldc + cb) = make_float2(v[0], v[1]);
            *reinterpret_cast<float2*>(C + r1 * ldc + cb) = make_float2(v[2], v[3]);
        }
    }
}

// ---------------------------------------------------------------------------
__global__ void softmax512(float* __restrict__ att)
{
    __shared__ float red[256];
    const long row = blockIdx.x;
    float* p = att + row * 512;
    const int t = threadIdx.x;
    float a = p[t];
    float b = p[t + 256];
    red[t] = fmaxf(a, b);
    __syncthreads();
    for (int s = 128; s > 0; s >>= 1) {
        if (t < s) red[t] = fmaxf(red[t], red[t + s]);
        __syncthreads();
    }
    const float m = red[0];
    __syncthreads();
    float e0 = __expf(a - m);
    float e1 = __expf(b - m);
    red[t] = e0 + e1;
    __syncthreads();
    for (int s = 128; s > 0; s >>= 1) {
        if (t < s) red[t] += red[t + s];
        __syncthreads();
    }
    const float inv = 1.f / red[0];
    p[t]       = e0 * inv;
    p[t + 256] = e1 * inv;
}

// ---------------------------------------------------------------------------
extern "C" void kernel_launch(void* const* d_in, const int* in_sizes, int n_in,
                              void* d_out, int out_size)
{
    const float* x      = (const float*)d_in[0];
    const float* adj    = (const float*)d_in[1];
    const float* gc_w   = (const float*)d_in[2];
    const float* gc_b   = (const float*)d_in[3];
    const float* bn1g   = (const float*)d_in[4];
    const float* bn1b   = (const float*)d_in[5];
    const float* bn1m   = (const float*)d_in[6];
    const float* bn1v   = (const float*)d_in[7];
    const float* gat_w  = (const float*)d_in[8];
    const float* conv_w = (const float*)d_in[9];
    const float* conv_b = (const float*)d_in[10];
    const float* bn2g   = (const float*)d_in[11];
    const float* bn2b   = (const float*)d_in[12];
    const float* bn2m   = (const float*)d_in[13];
    const float* bn2v   = (const float*)d_in[14];
    float* out = (float*)d_out;

    float *sup, *g, *hh, *att, *o;
    cudaGetSymbolAddress((void**)&sup, g_support);
    cudaGetSymbolAddress((void**)&g,   g_gact);
    cudaGetSymbolAddress((void**)&hh,  g_hh);
    cudaGetSymbolAddress((void**)&att, g_att);
    cudaGetSymbolAddress((void**)&o,   g_o);

    const long sNH = (long)NNODE * HID;
    const long sNO = (long)NNODE * OUTC;
    const long sBH = (long)NHEAD * NNODE * NNODE;
    const long sNN = (long)NNODE * NNODE;

    // 1) support = x @ gc_w (B staged transpose)
    tc_gemm<1, 0, false><<<dim3(4, 128, 1), 256>>>(
        x, FIN, 0, 0, gc_w, HID, 0, 0, sup, HID, 0, 0, FIN, 1,
        nullptr, nullptr, nullptr, nullptr, nullptr);

    // 2) g = relu(bn1(adj @ support + gc_b)) per batch (B staged)
    tc_gemm<1, 1, false><<<dim3(4, 4, BB), 256>>>(
        adj, NNODE, 0, 0, sup, HID, sNH, 0, g, HID, sNH, 0, NNODE, 1,
        gc_b, bn1g, bn1b, bn1m, bn1v);

    // 3) hh = g @ gat_w^T per batch (B direct)
    tc_gemm<0, 0, false><<<dim3(4, 4, BB), 256>>>(
        g, HID, sNH, 0, gat_w, HID, 0, 0, hh, OUTC, sNO, 0, HID, 1,
        nullptr, nullptr, nullptr, nullptr, nullptr);

    // 4) logits = leaky(hh_h @ hh_h^T) per (b,h) (B direct)
    tc_gemm<0, 2, false><<<dim3(4, 4, BB * NHEAD), 256>>>(
        hh, OUTC, sNO, DH, hh, OUTC, sNO, DH,
        att, NNODE, sBH, sNN, DH, NHEAD,
        nullptr, nullptr, nullptr, nullptr, nullptr);

    // 5) row softmax
    softmax512<<<BB * NHEAD * NNODE, 256>>>(att);

    // 6) o = att @ hh_h per (b,h) (B staged)
    tc_gemm<1, 0, false><<<dim3(1, 4, BB * NHEAD), 256>>>(
        att, NNODE, sBH, sNN, hh, OUTC, sNO, DH,
        o, OUTC, sNO, DH, NNODE, NHEAD,
        nullptr, nullptr, nullptr, nullptr, nullptr);

    // 7) conv1d(k=3,p=1) + bias + bn2 + relu -> out [B,N,OUT]
    tc_gemm<2, 1, true><<<dim3(4, 4, BB), 256>>>(
        o, OUTC, sNO, 0, conv_w, 0, 0, 0, out, OUTC, (long)NNODE * OUTC, 0,
        3 * OUTC, 1,
        conv_b, bn2g, bn2b, bn2m, bn2v);
}

// round 7
// speedup vs baseline: 1.7147x; 1.0257x over previous
#include <cuda_runtime.h>
#include <cuda_bf16.h>
#include <cstdint>

// Problem dims
#define BB    32
#define NNODE 512
#define FIN   256
#define HID   512
#define OUTC  512
#define NHEAD 4
#define DH    128
#define EPSV  1e-5f

#define KC    32          // k-chunk (elements) per smem stage
#define BUFSZ 32768       // one buffer set: AH|AL|BH|BL planes of 8KB

// Scratch (device globals: allocation-free)
__device__ float g_support[(size_t)BB * NNODE * HID];
__device__ float g_gact[(size_t)BB * NNODE * HID];
__device__ float g_hh[(size_t)BB * NNODE * OUTC];
__device__ float g_att[(size_t)BB * NHEAD * NNODE * NNODE];
__device__ float g_o[(size_t)BB * NNODE * OUTC];

__device__ __forceinline__ void mma16816(float* c, const uint32_t* a, const uint32_t* b) {
    asm volatile(
        "mma.sync.aligned.m16n8k16.row.col.f32.bf16.bf16.f32 "
        "{%0,%1,%2,%3}, {%4,%5,%6,%7}, {%8,%9}, {%0,%1,%2,%3};"
        : "+f"(c[0]), "+f"(c[1]), "+f"(c[2]), "+f"(c[3])
        : "r"(a[0]), "r"(a[1]), "r"(a[2]), "r"(a[3]), "r"(b[0]), "r"(b[1]));
}

__device__ __forceinline__ void split_bf16(float x, __nv_bfloat16& h, __nv_bfloat16& l) {
    h = __float2bfloat16_rn(x);
    l = __float2bfloat16_rn(x - __bfloat162float(h));
}

// swizzled plane layout: 128 rows x 64B (4 chunks of 8 bf16).
// chunk placed at (chunk ^ ((row>>1)&3)) -> conflict-free for 16B stores and ldmatrix.
__device__ __forceinline__ uint32_t sw_off(int row, int chunk) {
    return (uint32_t)((row << 6) + (((chunk) ^ ((row >> 1) & 3)) << 4));
}

__device__ __forceinline__ void ldm_x4(uint32_t& r0, uint32_t& r1, uint32_t& r2, uint32_t& r3,
                                       uint32_t a) {
    asm volatile("ldmatrix.sync.aligned.m8n8.x4.shared.b16 {%0,%1,%2,%3}, [%4];"
                 : "=r"(r0), "=r"(r1), "=r"(r2), "=r"(r3) : "r"(a));
}

// ---------------------------------------------------------------------------
// bf16x3 GEMM, double-buffered pipeline: C[128,128] tile = A @ B^T (+epilogue).
// 256 threads, 8 warps 4x2 (warp tile 32x64).
// BMODE: 0 = B rows K-major direct, 1 = B staged transpose ([K,N] src),
//        2 = conv weights w[co,ci,kpos] (stride-3 gather)
// CONV:  A rows shifted by (kpos-1), zero-padded; 48 K-steps (3 x 16).
// EPI:   0 none, 1 (v+bias-m)*s+b then ReLU, 2 LeakyReLU(0.2)
// ---------------------------------------------------------------------------
template <int BMODE, int EPI, bool CONV>
__global__ void __launch_bounds__(256, 2) tc_gemm(
    const float* __restrict__ A, int lda, long sA1, long sA2,
    const float* __restrict__ Bsrc, int ldb, long sB1, long sB2,
    float* __restrict__ C, int ldc, long sC1, long sC2,
    int K, int zdiv,
    const float* __restrict__ bias,
    const float* __restrict__ bng, const float* __restrict__ bnb,
    const float* __restrict__ bnm, const float* __restrict__ bnv)
{
    __shared__ __align__(16) unsigned char sm[2 * BUFSZ];  // double buffer
    unsigned char* const smp = sm;
    const uint32_t smb = (uint32_t)__cvta_generic_to_shared(sm);

    const int z  = blockIdx.z;
    const int z1 = z / zdiv;
    const int z2 = z - z1 * zdiv;
    A    += (long)z1 * sA1 + (long)z2 * sA2;
    Bsrc += (long)z1 * sB1 + (long)z2 * sB2;
    C    += (long)z1 * sC1 + (long)z2 * sC2;

    const int m0 = blockIdx.y * 128;
    const int n0 = blockIdx.x * 128;
    const int tid = threadIdx.x;

    const int w    = tid >> 5;
    const int lane = tid & 31;
    const int gq   = lane >> 2;
    const int tig  = lane & 3;
    const int wm   = (w >> 1) * 32;  // warp m offset
    const int wn   = (w & 1) * 64;   // warp n offset

    // staging indices
    const int ar  = tid >> 1;         // 0..127 row
    const int ac0 = (tid & 1) * 16;   // k base
    const int bkk = tid >> 3;         // 0..31 (transpose: k col)
    const int ba  = tid & 7;
    const int bj0 = ba * 16;

    float acc[2][8][4];
#pragma unroll
    for (int i = 0; i < 2; i++)
#pragma unroll
        for (int j = 0; j < 8; j++)
#pragma unroll
            for (int q = 0; q < 4; q++) acc[i][j][q] = 0.f;

    const int steps = CONV ? 48 : (K >> 5);

    float av[16], bv[16];

    auto loadA = [&](int s) {
        int k0, shift;
        if (CONV) { shift = s >> 4; k0 = (s & 15) * KC; }
        else      { shift = 0;      k0 = s * KC; }
        bool valid = true;
        long row = m0 + ar;
        if (CONV) {
            int rs = m0 + ar + shift - 1;
            valid = (rs >= 0) && (rs < NNODE);
            row = rs;
        }
        const float4* ap = reinterpret_cast<const float4*>(A + row * lda + k0 + ac0);
#pragma unroll
        for (int j = 0; j < 4; j++) {
            float4 v = valid ? ap[j] : make_float4(0.f, 0.f, 0.f, 0.f);
            av[4 * j + 0] = v.x; av[4 * j + 1] = v.y;
            av[4 * j + 2] = v.z; av[4 * j + 3] = v.w;
        }
    };

    auto loadB = [&](int s) {
        int k0, shift;
        if (CONV) { shift = s >> 4; k0 = (s & 15) * KC; }
        else      { shift = 0;      k0 = s * KC; }
        if (BMODE == 0) {
            const float4* bp = reinterpret_cast<const float4*>(Bsrc + (long)(n0 + ar) * ldb + k0 + ac0);
#pragma unroll
            for (int j = 0; j < 4; j++) {
                float4 v = bp[j];
                bv[4 * j + 0] = v.x; bv[4 * j + 1] = v.y;
                bv[4 * j + 2] = v.z; bv[4 * j + 3] = v.w;
            }
        } else if (BMODE == 1) {
            const float4* bp = reinterpret_cast<const float4*>(Bsrc + (long)(k0 + bkk) * ldb + n0 + bj0);
#pragma unroll
            for (int q = 0; q < 4; q++) {
                float4 v = bp[q];
                bv[4 * q + 0] = v.x; bv[4 * q + 1] = v.y;
                bv[4 * q + 2] = v.z; bv[4 * q + 3] = v.w;
            }
        } else {
#pragma unroll
            for (int j = 0; j < 16; j++) {
                int ci = k0 + ac0 + j;
                bv[j] = Bsrc[(long)(n0 + ar) * (OUTC * 3) + (long)ci * 3 + shift];
            }
        }
    };

    auto stage = [&](uint32_t bufo) {
        unsigned char* const sp = smp + bufo;
        const int c0 = ac0 >> 3;
#pragma unroll
        for (int cj = 0; cj < 2; cj++) {
            union { uint4 u; __nv_bfloat16 h[8]; } ph, pl;
#pragma unroll
            for (int q = 0; q < 8; q++) split_bf16(av[cj * 8 + q], ph.h[q], pl.h[q]);
            const uint32_t off = sw_off(ar, c0 + cj);
            *reinterpret_cast<uint4*>(sp + off)        = ph.u;
            *reinterpret_cast<uint4*>(sp + 8192 + off) = pl.u;
        }
        if (BMODE == 0 || BMODE == 2) {
#pragma unroll
            for (int cj = 0; cj < 2; cj++) {
                union { uint4 u; __nv_bfloat16 h[8]; } ph, pl;
#pragma unroll
                for (int q = 0; q < 8; q++) split_bf16(bv[cj * 8 + q], ph.h[q], pl.h[q]);
                const uint32_t off = sw_off(ar, c0 + cj);
                *reinterpret_cast<uint4*>(sp + 16384 + off) = ph.u;
                *reinterpret_cast<uint4*>(sp + 24576 + off) = pl.u;
            }
        } else {
            const uint32_t cb = ((uint32_t)(bkk >> 3) << 4) + (uint32_t)(bkk & 7) * 2;
#pragma unroll
            for (int j = 0; j < 16; j++) {
                const int idx = (j + ba) & 15;
                const int row = bj0 + idx;
                __nv_bfloat16 h, l;
                split_bf16(bv[idx], h, l);
                const uint32_t off = (uint32_t)(row << 6)
                    + ((cb & ~15u) ^ (((uint32_t)((row >> 1) & 3)) << 4)) + (cb & 15u);
                *reinterpret_cast<__nv_bfloat16*>(sp + 16384 + off) = h;
                *reinterpret_cast<__nv_bfloat16*>(sp + 24576 + off) = l;
            }
        }
    };

    auto compute = [&](uint32_t bufo) {
        const uint32_t AHs = smb + bufo, ALs = AHs + 8192;
        const uint32_t BHs = AHs + 16384, BLs = AHs + 24576;
#pragma unroll
        for (int ks = 0; ks < 2; ks++) {
            const int kc = ks * 2;
            uint32_t afh[2][4], afl[2][4];
            const int arow = wm + (lane & 15);
            const int achk = kc + (lane >> 4);
#pragma unroll
            for (int mt = 0; mt < 2; mt++) {
                const uint32_t off = sw_off(arow + mt * 16, achk);
                ldm_x4(afh[mt][0], afh[mt][1], afh[mt][2], afh[mt][3], AHs + off);
                ldm_x4(afl[mt][0], afl[mt][1], afl[mt][2], afl[mt][3], ALs + off);
            }
            const int brow_b = wn + (lane & 7) + ((lane >> 4) << 3);
            const int bchk = kc + ((lane >> 3) & 1);
#pragma unroll
            for (int ntp = 0; ntp < 4; ntp++) {
                const uint32_t off = sw_off(brow_b + ntp * 16, bchk);
                uint32_t bh[4], bl[4];
                ldm_x4(bh[0], bh[1], bh[2], bh[3], BHs + off);
                ldm_x4(bl[0], bl[1], bl[2], bl[3], BLs + off);
#pragma unroll
                for (int hf = 0; hf < 2; hf++) {
                    const int nt = ntp * 2 + hf;
                    uint32_t bfh[2] = {bh[hf * 2], bh[hf * 2 + 1]};
                    uint32_t bfl[2] = {bl[hf * 2], bl[hf * 2 + 1]};
#pragma unroll
                    for (int mt = 0; mt < 2; mt++) {
                        mma16816(acc[mt][nt], afh[mt], bfh);
                        mma16816(acc[mt][nt], afh[mt], bfl);
                        mma16816(acc[mt][nt], afl[mt], bfh);
                    }
                }
            }
        }
    };

    // ---- pipelined mainloop: 1 barrier per step ----
    loadA(0); loadB(0);
    stage(0);
    __syncthreads();
    for (int s = 0; s < steps; s++) {
        const uint32_t cur = (uint32_t)(s & 1) * BUFSZ;
        const uint32_t nxt = (uint32_t)((s + 1) & 1) * BUFSZ;
        if (s + 1 < steps) { loadA(s + 1); loadB(s + 1); }
        compute(cur);
        if (s + 1 < steps) stage(nxt);
        __syncthreads();
    }

    // ---- epilogue ----
#pragma unroll
    for (int mt = 0; mt < 2; mt++) {
        const long r0 = m0 + wm + mt * 16 + gq;
        const long r1 = r0 + 8;
#pragma unroll
        for (int nt = 0; nt < 8; nt++) {
            const int cb = n0 + wn + nt * 8 + 2 * tig;
            float v[4] = {acc[mt][nt][0], acc[mt][nt][1], acc[mt][nt][2], acc[mt][nt][3]};
            if (EPI == 1) {
#pragma unroll
                for (int q = 0; q < 4; q++) {
                    const int n = cb + (q & 1);
                    float sc = bng[n] * rsqrtf(bnv[n] + EPSV);
                    v[q] = (v[q] + bias[n] - bnm[n]) * sc + bnb[n];
                    v[q] = fmaxf(v[q], 0.f);
                }
            } else if (EPI == 2) {
#pragma unroll
                for (int q = 0; q < 4; q++) v[q] = (v[q] > 0.f) ? v[q] : 0.2f * v[q];
            }
            *reinterpret_cast<float2*>(C + r0 * ldc + cb) = make_float2(v[0], v[1]);
            *reinterpret_cast<float2*>(C + r1 * ldc + cb) = make_float2(v[2], v[3]);
        }
    }
}

// ---------------------------------------------------------------------------
__global__ void softmax512(float* __restrict__ att)
{
    __shared__ float red[256];
    const long row = blockIdx.x;
    float* p = att + row * 512;
    const int t = threadIdx.x;
    float a = p[t];
    float b = p[t + 256];
    red[t] = fmaxf(a, b);
    __syncthreads();
    for (int s = 128; s > 0; s >>= 1) {
        if (t < s) red[t] = fmaxf(red[t], red[t + s]);
        __syncthreads();
    }
    const float m = red[0];
    __syncthreads();
    float e0 = __expf(a - m);
    float e1 = __expf(b - m);
    red[t] = e0 + e1;
    __syncthreads();
    for (int s = 128; s > 0; s >>= 1) {
        if (t < s) red[t] += red[t + s];
        __syncthreads();
    }
    const float inv = 1.f / red[0];
    p[t]       = e0 * inv;
    p[t + 256] = e1 * inv;
}

// ---------------------------------------------------------------------------
extern "C" void kernel_launch(void* const* d_in, const int* in_sizes, int n_in,
                              void* d_out, int out_size)
{
    const float* x      = (const float*)d_in[0];
    const float* adj    = (const float*)d_in[1];
    const float* gc_w   = (const float*)d_in[2];
    const float* gc_b   = (const float*)d_in[3];
    const float* bn1g   = (const float*)d_in[4];
    const float* bn1b   = (const float*)d_in[5];
    const float* bn1m   = (const float*)d_in[6];
    const float* bn1v   = (const float*)d_in[7];
    const float* gat_w  = (const float*)d_in[8];
    const float* conv_w = (const float*)d_in[9];
    const float* conv_b = (const float*)d_in[10];
    const float* bn2g   = (const float*)d_in[11];
    const float* bn2b   = (const float*)d_in[12];
    const float* bn2m   = (const float*)d_in[13];
    const float* bn2v   = (const float*)d_in[14];
    float* out = (float*)d_out;

    float *sup, *g, *hh, *att, *o;
    cudaGetSymbolAddress((void**)&sup, g_support);
    cudaGetSymbolAddress((void**)&g,   g_gact);
    cudaGetSymbolAddress((void**)&hh,  g_hh);
    cudaGetSymbolAddress((void**)&att, g_att);
    cudaGetSymbolAddress((void**)&o,   g_o);

    const long sNH = (long)NNODE * HID;
    const long sNO = (long)NNODE * OUTC;
    const long sBH = (long)NHEAD * NNODE * NNODE;
    const long sNN = (long)NNODE * NNODE;

    // 1) support = x @ gc_w (B staged transpose)
    tc_gemm<1, 0, false><<<dim3(4, 128, 1), 256>>>(
        x, FIN, 0, 0, gc_w, HID, 0, 0, sup, HID, 0, 0, FIN, 1,
        nullptr, nullptr, nullptr, nullptr, nullptr);

    // 2) g = relu(bn1(adj @ support + gc_b)) per batch (B staged)
    tc_gemm<1, 1, false><<<dim3(4, 4, BB), 256>>>(
        adj, NNODE, 0, 0, sup, HID, sNH, 0, g, HID, sNH, 0, NNODE, 1,
        gc_b, bn1g, bn1b, bn1m, bn1v);

    // 3) hh = g @ gat_w^T per batch (B direct)
    tc_gemm<0, 0, false><<<dim3(4, 4, BB), 256>>>(
        g, HID, sNH, 0, gat_w, HID, 0, 0, hh, OUTC, sNO, 0, HID, 1,
        nullptr, nullptr, nullptr, nullptr, nullptr);

    // 4) logits = leaky(hh_h @ hh_h^T) per (b,h) (B direct)
    tc_gemm<0, 2, false><<<dim3(4, 4, BB * NHEAD), 256>>>(
        hh, OUTC, sNO, DH, hh, OUTC, sNO, DH,
        att, NNODE, sBH, sNN, DH, NHEAD,
        nullptr, nullptr, nullptr, nullptr, nullptr);

    // 5) row softmax
    softmax512<<<BB * NHEAD * NNODE, 256>>>(att);

    // 6) o = att @ hh_h per (b,h) (B staged)
    tc_gemm<1, 0, false><<<dim3(1, 4, BB * NHEAD), 256>>>(
        att, NNODE, sBH, sNN, hh, OUTC, sNO, DH,
        o, OUTC, sNO, DH, NNODE, NHEAD,
        nullptr, nullptr, nullptr, nullptr, nullptr);

    // 7) conv1d(k=3,p=1) + bias + bn2 + relu -> out [B,N,OUT]
    tc_gemm<2, 1, true><<<dim3(4, 4, BB), 256>>>(
        o, OUTC, sNO, 0, conv_w, 0, 0, 0, out, OUTC, (long)NNODE * OUTC, 0,
        3 * OUTC, 1,
        conv_b, bn2g, bn2b, bn2m, bn2v);
}

// round 9
// speedup vs baseline: 2.5510x; 1.4877x over previous
#include <cuda_runtime.h>
#include <cuda_bf16.h>
#include <cstdint>

// Problem dims
#define BB    32
#define NNODE 512
#define FIN   256
#define HID   512
#define OUTC  512
#define NHEAD 4
#define DH    128
#define EPSV  1e-5f

#define KC    32          // k elements per smem stage
#define BUFSZ 32768       // AH|AL|BH|BL planes of 8KB each

// ---------------- pre-split bf16 hi/lo planes (device globals) -------------
#define NX   ((size_t)16384 * 256)
#define NADJ ((size_t)512 * 512)
#define NGW  ((size_t)512 * 256)
#define NGAT ((size_t)512 * 512)
#define NCW  ((size_t)3 * 512 * 512)
#define SNO  ((size_t)512 * 512)          // 262144

__device__ __align__(16) __nv_bfloat16 g_xph[NX],   g_xpl[NX];
__device__ __align__(16) __nv_bfloat16 g_adjh[NADJ], g_adjl[NADJ];
__device__ __align__(16) __nv_bfloat16 g_gwth[NGW], g_gwtl[NGW];      // gc_w^T [512][256]
__device__ __align__(16) __nv_bfloat16 g_gath[NGAT], g_gatl[NGAT];    // gat_w [512][512]
__device__ __align__(16) __nv_bfloat16 g_cwh[NCW],  g_cwl[NCW];       // [kpos][co][ci]
__device__ __align__(16) __nv_bfloat16 g_suth[(size_t)512 * 16384], g_sutl[(size_t)512 * 16384];
__device__ __align__(16) __nv_bfloat16 g_gh[(size_t)BB * SNO],  g_gl[(size_t)BB * SNO];
__device__ __align__(16) __nv_bfloat16 g_hhh[(size_t)BB * SNO], g_hhl[(size_t)BB * SNO];
__device__ __align__(16) __nv_bfloat16 g_hth[(size_t)BB * SNO], g_htl[(size_t)BB * SNO];  // hh^T per batch
__device__ __align__(16) __nv_bfloat16 g_ath[(size_t)128 * SNO], g_atl[(size_t)128 * SNO];
__device__ __align__(16) __nv_bfloat16 g_oh[(size_t)BB * SNO],  g_ol[(size_t)BB * SNO];
__device__ float g_att[(size_t)128 * SNO];    // fp32 logits/probs

// ---------------------------------------------------------------------------
__device__ __forceinline__ void mma16816(float* c, const uint32_t* a, const uint32_t* b) {
    asm volatile(
        "mma.sync.aligned.m16n8k16.row.col.f32.bf16.bf16.f32 "
        "{%0,%1,%2,%3}, {%4,%5,%6,%7}, {%8,%9}, {%0,%1,%2,%3};"
        : "+f"(c[0]), "+f"(c[1]), "+f"(c[2]), "+f"(c[3])
        : "r"(a[0]), "r"(a[1]), "r"(a[2]), "r"(a[3]), "r"(b[0]), "r"(b[1]));
}
__device__ __forceinline__ void split_bf16(float x, __nv_bfloat16& h, __nv_bfloat16& l) {
    h = __float2bfloat16_rn(x);
    l = __float2bfloat16_rn(x - __bfloat162float(h));
}
__device__ __forceinline__ uint32_t sw_off(int row, int chunk) {
    return (uint32_t)((row << 6) + (((chunk) ^ ((row >> 1) & 3)) << 4));
}
__device__ __forceinline__ void ldm_x4(uint32_t& r0, uint32_t& r1, uint32_t& r2, uint32_t& r3,
                                       uint32_t a) {
    asm volatile("ldmatrix.sync.aligned.m8n8.x4.shared.b16 {%0,%1,%2,%3}, [%4];"
                 : "=r"(r0), "=r"(r1), "=r"(r2), "=r"(r3) : "r"(a));
}
__device__ __forceinline__ void cp16(uint32_t dst, const void* src, int sz) {
    asm volatile("cp.async.cg.shared.global [%0], [%1], 16, %2;"
                 :: "r"(dst), "l"(src), "r"(sz) : "memory");
}
__device__ __forceinline__ void cp_commit() {
    asm volatile("cp.async.commit_group;" ::: "memory");
}
template <int N>
__device__ __forceinline__ void cp_wait() {
    asm volatile("cp.async.wait_group %0;" :: "n"(N) : "memory");
}

// ---------------------------------------------------------------------------
// Pre-split GEMM, cp.async double-buffered. C[128,128] tile = A @ B^T.
// All operands are bf16 hi/lo planes, K-major.
// CONV: A rows shifted by (kpos-1), zero-padded; B gets +shift*SNO plane offset;
//       48 K-steps (3 x 16).
// EPI: 0 none, 1 (v+bias-m)*s+b then ReLU, 2 LeakyReLU(0.2)
// OUT: 0 = write split bf16 planes (Ch/Cl), 1 = write fp32 (Cf)
// ---------------------------------------------------------------------------
template <int EPI, int OUT, bool CONV>
__global__ void __launch_bounds__(256, 2) gemm_p(
    const __nv_bfloat16* __restrict__ Ah, const __nv_bfloat16* __restrict__ Al,
    int lda, long sA1, long sA2,
    const __nv_bfloat16* __restrict__ Bh, const __nv_bfloat16* __restrict__ Bl,
    int ldb, long sB1, long sB2,
    float* __restrict__ Cf, __nv_bfloat16* __restrict__ Ch, __nv_bfloat16* __restrict__ Cl,
    int ldc, long sC1, long sC2,
    int K, int zdiv,
    const float* __restrict__ bias,
    const float* __restrict__ bng, const float* __restrict__ bnb,
    const float* __restrict__ bnm, const float* __restrict__ bnv)
{
    __shared__ __align__(16) unsigned char sm[2 * BUFSZ];
    const uint32_t smb = (uint32_t)__cvta_generic_to_shared(sm);

    const int z  = blockIdx.z;
    const int z1 = z / zdiv;
    const int z2 = z - z1 * zdiv;
    Ah += z1 * sA1 + z2 * sA2;  Al += z1 * sA1 + z2 * sA2;
    Bh += z1 * sB1 + z2 * sB2;  Bl += z1 * sB1 + z2 * sB2;
    if (OUT == 1) Cf += z1 * sC1 + z2 * sC2;
    else { Ch += z1 * sC1 + z2 * sC2; Cl += z1 * sC1 + z2 * sC2; }

    const int m0 = blockIdx.y * 128;
    const int n0 = blockIdx.x * 128;
    const int tid = threadIdx.x;

    const int w    = tid >> 5;
    const int lane = tid & 31;
    const int gq   = lane >> 2;
    const int tig  = lane & 3;
    const int wm   = (w >> 1) * 32;
    const int wn   = (w & 1) * 64;

    float acc[2][8][4];
#pragma unroll
    for (int i = 0; i < 2; i++)
#pragma unroll
        for (int j = 0; j < 8; j++)
#pragma unroll
            for (int q = 0; q < 4; q++) acc[i][j][q] = 0.f;

    const int steps = CONV ? 48 : (K >> 5);

    // stage k-chunk s into buffer: 8 cp.async 16B per thread
    auto stageAsync = [&](int s, uint32_t bufo) {
        int k0, shift;
        if (CONV) { shift = s >> 4; k0 = (s & 15) * KC; }
        else      { shift = 0;      k0 = s * KC; }
        const uint32_t base = smb + bufo;
#pragma unroll
        for (int rep = 0; rep < 2; rep++) {
            const int c   = tid + rep * 256;   // 0..511
            const int row = c >> 2;
            const int kc  = c & 3;
            const uint32_t off = sw_off(row, kc);
            // A planes
            {
                long arow = m0 + row;
                int sz = 16;
                if (CONV) {
                    int rs = m0 + row + shift - 1;
                    if (rs < 0 || rs >= NNODE) { sz = 0; rs = 0; }
                    arow = rs;
                }
                const long so = arow * (long)lda + k0 + kc * 8;
                cp16(base + off,        Ah + so, sz);
                cp16(base + 8192 + off, Al + so, sz);
            }
            // B planes
            {
                const long so = (CONV ? (long)shift * (long)SNO : 0L)
                              + (long)(n0 + row) * (long)ldb + k0 + kc * 8;
                cp16(base + 16384 + off, Bh + so, 16);
                cp16(base + 24576 + off, Bl + so, 16);
            }
        }
    };

    auto compute = [&](uint32_t bufo) {
        const uint32_t AHs = smb + bufo, ALs = AHs + 8192;
        const uint32_t BHs = AHs + 16384, BLs = AHs + 24576;
#pragma unroll
        for (int ks = 0; ks < 2; ks++) {
            const int kc = ks * 2;
            uint32_t afh[2][4], afl[2][4];
            const int arow = wm + (lane & 15);
            const int achk = kc + (lane >> 4);
#pragma unroll
            for (int mt = 0; mt < 2; mt++) {
                const uint32_t off = sw_off(arow + mt * 16, achk);
                ldm_x4(afh[mt][0], afh[mt][1], afh[mt][2], afh[mt][3], AHs + off);
                ldm_x4(afl[mt][0], afl[mt][1], afl[mt][2], afl[mt][3], ALs + off);
            }
            const int brow_b = wn + (lane & 7) + ((lane >> 4) << 3);
            const int bchk = kc + ((lane >> 3) & 1);
#pragma unroll
            for (int ntp = 0; ntp < 4; ntp++) {
                const uint32_t off = sw_off(brow_b + ntp * 16, bchk);
                uint32_t bh[4], bl[4];
                ldm_x4(bh[0], bh[1], bh[2], bh[3], BHs + off);
                ldm_x4(bl[0], bl[1], bl[2], bl[3], BLs + off);
#pragma unroll
                for (int hf = 0; hf < 2; hf++) {
                    const int nt = ntp * 2 + hf;
                    uint32_t bfh[2] = {bh[hf * 2], bh[hf * 2 + 1]};
                    uint32_t bfl[2] = {bl[hf * 2], bl[hf * 2 + 1]};
#pragma unroll
                    for (int mt = 0; mt < 2; mt++) {
                        mma16816(acc[mt][nt], afh[mt], bfh);
                        mma16816(acc[mt][nt], afh[mt], bfl);
                        mma16816(acc[mt][nt], afl[mt], bfh);
                    }
                }
            }
        }
    };

    // ---- async pipelined mainloop ----
    stageAsync(0, 0);
    cp_commit();
    for (int s = 0; s < steps; s++) {
        const uint32_t cur = (uint32_t)(s & 1) * BUFSZ;
        if (s + 1 < steps) {
            stageAsync(s + 1, (uint32_t)((s + 1) & 1) * BUFSZ);
            cp_commit();
            cp_wait<1>();
        } else {
            cp_wait<0>();
        }
        __syncthreads();
        compute(cur);
        __syncthreads();
    }

    // ---- epilogue ----
#pragma unroll
    for (int mt = 0; mt < 2; mt++) {
        const long r0 = m0 + wm + mt * 16 + gq;
        const long r1 = r0 + 8;
#pragma unroll
        for (int nt = 0; nt < 8; nt++) {
            const int cb = n0 + wn + nt * 8 + 2 * tig;
            float v[4] = {acc[mt][nt][0], acc[mt][nt][1], acc[mt][nt][2], acc[mt][nt][3]};
            if (EPI == 1) {
#pragma unroll
                for (int q = 0; q < 4; q++) {
                    const int n = cb + (q & 1);
                    float sc = bng[n] * rsqrtf(bnv[n] + EPSV);
                    v[q] = (v[q] + bias[n] - bnm[n]) * sc + bnb[n];
                    v[q] = fmaxf(v[q], 0.f);
                }
            } else if (EPI == 2) {
#pragma unroll
                for (int q = 0; q < 4; q++) v[q] = (v[q] > 0.f) ? v[q] : 0.2f * v[q];
            }
            if (OUT == 1) {
                *reinterpret_cast<float2*>(Cf + r0 * ldc + cb) = make_float2(v[0], v[1]);
                *reinterpret_cast<float2*>(Cf + r1 * ldc + cb) = make_float2(v[2], v[3]);
            } else {
                __nv_bfloat16 h0, l0, h1, l1;
                split_bf16(v[0], h0, l0); split_bf16(v[1], h1, l1);
                __nv_bfloat162 ph, pl;
                ph.x = h0; ph.y = h1; pl.x = l0; pl.y = l1;
                *reinterpret_cast<__nv_bfloat162*>(Ch + r0 * ldc + cb) = ph;
                *reinterpret_cast<__nv_bfloat162*>(Cl + r0 * ldc + cb) = pl;
                split_bf16(v[2], h0, l0); split_bf16(v[3], h1, l1);
                ph.x = h0; ph.y = h1; pl.x = l0; pl.y = l1;
                *reinterpret_cast<__nv_bfloat162*>(Ch + r1 * ldc + cb) = ph;
                *reinterpret_cast<__nv_bfloat162*>(Cl + r1 * ldc + cb) = pl;
            }
        }
    }
}

// ---------------------------------------------------------------------------
// prep: split raw fp32 inputs into bf16 hi/lo planes (with needed transposes)
// ---------------------------------------------------------------------------
__global__ void prep(const float* __restrict__ x, const float* __restrict__ adj,
                     const float* __restrict__ gc_w, const float* __restrict__ gat_w,
                     const float* __restrict__ conv_w)
{
    long i = (long)blockIdx.x * 256 + threadIdx.x;
    float v; __nv_bfloat16 h, l;
    if (i < (long)NX) {
        v = x[i]; split_bf16(v, h, l); g_xph[i] = h; g_xpl[i] = l; return;
    }
    i -= NX;
    if (i < (long)NADJ) {
        v = adj[i]; split_bf16(v, h, l); g_adjh[i] = h; g_adjl[i] = l; return;
    }
    i -= NADJ;
    if (i < (long)NGW) {       // gwt[d][c] = gc_w[c][d]
        long d = i >> 8, c = i & 255;
        v = gc_w[c * 512 + d]; split_bf16(v, h, l); g_gwth[i] = h; g_gwtl[i] = l; return;
    }
    i -= NGW;
    if (i < (long)NGAT) {
        v = gat_w[i]; split_bf16(v, h, l); g_gath[i] = h; g_gatl[i] = l; return;
    }
    i -= NGAT;
    if (i < (long)NCW) {       // cw[kpos][co][ci] = conv_w[co][ci][kpos]
        long kpos = i / 262144, r = i % 262144;
        long co = r >> 9, ci = r & 511;
        v = conv_w[co * 1536 + ci * 3 + kpos];
        split_bf16(v, h, l); g_cwh[i] = h; g_cwl[i] = l; return;
    }
}

// ---------------------------------------------------------------------------
// transpose hh planes per batch: hhT[b][d][n] = hh[b][n][d]   (512x512)
// ---------------------------------------------------------------------------
__global__ void transp(const __nv_bfloat16* __restrict__ src_h,
                       const __nv_bfloat16* __restrict__ src_l,
                       __nv_bfloat16* __restrict__ dst_h,
                       __nv_bfloat16* __restrict__ dst_l)
{
    __shared__ __nv_bfloat16 t[64][65];
    const int b  = blockIdx.z;
    const int r0 = blockIdx.y * 64;
    const int c0 = blockIdx.x * 64;
    const long base = (long)b * SNO;
    const int col = threadIdx.x & 63;
    const int rw0 = threadIdx.x >> 6;           // 0..3
    for (int pl = 0; pl < 2; pl++) {
        const __nv_bfloat16* s = pl ? src_l : src_h;
        __nv_bfloat16* d = pl ? dst_l : dst_h;
        __syncthreads();
#pragma unroll
        for (int rr = 0; rr < 16; rr++) {
            const int r = rw0 + rr * 4;
            t[r][col] = s[base + (long)(r0 + r) * 512 + c0 + col];
        }
        __syncthreads();
#pragma unroll
        for (int rr = 0; rr < 16; rr++) {
            const int r = rw0 + rr * 4;
            d[base + (long)(c0 + r) * 512 + r0 + col] = t[col][r];
        }
    }
}

// ---------------------------------------------------------------------------
// Row softmax over 512 fp32 -> split bf16 planes
// ---------------------------------------------------------------------------
__global__ void softmax512(const float* __restrict__ att,
                           __nv_bfloat16* __restrict__ oh, __nv_bfloat16* __restrict__ ol)
{
    __shared__ float red[256];
    const long row = blockIdx.x;
    const float* p = att + row * 512;
    const int t = threadIdx.x;
    float a = p[t];
    float b = p[t + 256];
    red[t] = fmaxf(a, b);
    __syncthreads();
    for (int s = 128; s > 0; s >>= 1) {
        if (t < s) red[t] = fmaxf(red[t], red[t + s]);
        __syncthreads();
    }
    const float m = red[0];
    __syncthreads();
    float e0 = __expf(a - m);
    float e1 = __expf(b - m);
    red[t] = e0 + e1;
    __syncthreads();
    for (int s = 128; s > 0; s >>= 1) {
        if (t < s) red[t] += red[t + s];
        __syncthreads();
    }
    const float inv = 1.f / red[0];
    __nv_bfloat16 h, l;
    split_bf16(e0 * inv, h, l);
    oh[row * 512 + t] = h; ol[row * 512 + t] = l;
    split_bf16(e1 * inv, h, l);
    oh[row * 512 + t + 256] = h; ol[row * 512 + t + 256] = l;
}

// ---------------------------------------------------------------------------
extern "C" void kernel_launch(void* const* d_in, const int* in_sizes, int n_in,
                              void* d_out, int out_size)
{
    const float* x      = (const float*)d_in[0];
    const float* adj    = (const float*)d_in[1];
    const float* gc_w   = (const float*)d_in[2];
    const float* gc_b   = (const float*)d_in[3];
    const float* bn1g   = (const float*)d_in[4];
    const float* bn1b   = (const float*)d_in[5];
    const float* bn1m   = (const float*)d_in[6];
    const float* bn1v   = (const float*)d_in[7];
    const float* gat_w  = (const float*)d_in[8];
    const float* conv_w = (const float*)d_in[9];
    const float* conv_b = (const float*)d_in[10];
    const float* bn2g   = (const float*)d_in[11];
    const float* bn2b   = (const float*)d_in[12];
    const float* bn2m   = (const float*)d_in[13];
    const float* bn2v   = (const float*)d_in[14];
    float* out = (float*)d_out;

    __nv_bfloat16 *xph, *xpl, *adjh, *adjl, *gwth, *gwtl, *gath, *gatl, *cwh, *cwl;
    __nv_bfloat16 *suth, *sutl, *gh, *gl, *hhh, *hhl, *hth, *htl, *ath, *atl, *oh, *ol;
    float* att;
    cudaGetSymbolAddress((void**)&xph, g_xph);   cudaGetSymbolAddress((void**)&xpl, g_xpl);
    cudaGetSymbolAddress((void**)&adjh, g_adjh); cudaGetSymbolAddress((void**)&adjl, g_adjl);
    cudaGetSymbolAddress((void**)&gwth, g_gwth); cudaGetSymbolAddress((void**)&gwtl, g_gwtl);
    cudaGetSymbolAddress((void**)&gath, g_gath); cudaGetSymbolAddress((void**)&gatl, g_gatl);
    cudaGetSymbolAddress((void**)&cwh, g_cwh);   cudaGetSymbolAddress((void**)&cwl, g_cwl);
    cudaGetSymbolAddress((void**)&suth, g_suth); cudaGetSymbolAddress((void**)&sutl, g_sutl);
    cudaGetSymbolAddress((void**)&gh, g_gh);     cudaGetSymbolAddress((void**)&gl, g_gl);
    cudaGetSymbolAddress((void**)&hhh, g_hhh);   cudaGetSymbolAddress((void**)&hhl, g_hhl);
    cudaGetSymbolAddress((void**)&hth, g_hth);   cudaGetSymbolAddress((void**)&htl, g_htl);
    cudaGetSymbolAddress((void**)&ath, g_ath);   cudaGetSymbolAddress((void**)&atl, g_atl);
    cudaGetSymbolAddress((void**)&oh, g_oh);     cudaGetSymbolAddress((void**)&ol, g_ol);
    cudaGetSymbolAddress((void**)&att, g_att);

    const long total_prep = (long)(NX + NADJ + NGW + NGAT + NCW);

    // 0) split inputs
    prep<<<(unsigned)((total_prep + 255) / 256), 256>>>(x, adj, gc_w, gat_w, conv_w);

    // 1) supT[d][bn] = sum_c gwt[d][c] * x[bn][c]    (M=512, N=16384, K=256)
    gemm_p<0, 0, false><<<dim3(128, 4, 1), 256>>>(
        gwth, gwtl, 256, 0, 0,
        xph, xpl, 256, 0, 0,
        nullptr, suth, sutl, 16384, 0, 0,
        256, 1, nullptr, nullptr, nullptr, nullptr, nullptr);

    // 2) g[b] = relu(bn1(adj @ sup + gc_b)): A=adj, B=supT (rows d, K=m), per batch
    gemm_p<1, 0, false><<<dim3(4, 4, BB), 256>>>(
        adjh, adjl, 512, 0, 0,
        suth, sutl, 16384, 512, 0,
        nullptr, gh, gl, 512, (long)SNO, 0,
        512, 1, gc_b, bn1g, bn1b, bn1m, bn1v);

    // 3) hh[b] = g @ gat_w^T
    gemm_p<0, 0, false><<<dim3(4, 4, BB), 256>>>(
        gh, gl, 512, (long)SNO, 0,
        gath, gatl, 512, 0, 0,
        nullptr, hhh, hhl, 512, (long)SNO, 0,
        512, 1, nullptr, nullptr, nullptr, nullptr, nullptr);

    // 3b) hhT[b] = hh[b]^T
    transp<<<dim3(8, 8, BB), 256>>>(hhh, hhl, hth, htl);

    // 4) logits[b,h] = leaky(hh_h @ hh_h^T), K=128 slice at col h*128
    gemm_p<2, 1, false><<<dim3(4, 4, BB * NHEAD), 256>>>(
        hhh, hhl, 512, (long)SNO, 128,
        hhh, hhl, 512, (long)SNO, 128,
        att, nullptr, nullptr, 512, (long)(4 * SNO), (long)SNO,
        128, NHEAD, nullptr, nullptr, nullptr, nullptr, nullptr);

    // 5) softmax -> split att planes
    softmax512<<<128 * 512, 256>>>(att, ath, atl);

    // 6) o[b,h] = att @ hh_h : A=att planes (K=512), B=hhT rows h*128+d (K=m)
    gemm_p<0, 0, false><<<dim3(1, 4, BB * NHEAD), 256>>>(
        ath, atl, 512, (long)(4 * SNO), (long)SNO,
        hth, htl, 512, (long)SNO, (long)(128 * 512),
        nullptr, oh, ol, 512, (long)SNO, 128,
        512, NHEAD, nullptr, nullptr, nullptr, nullptr, nullptr);

    // 7) conv1d(k=3,p=1) + bias + bn2 + relu -> out fp32
    gemm_p<1, 1, true><<<dim3(4, 4, BB), 256>>>(
        oh, ol, 512, (long)SNO, 0,
        cwh, cwl, 512, 0, 0,
        out, nullptr, nullptr, 512, (long)SNO, 0,
        3 * 512, 1, conv_b, bn2g, bn2b, bn2m, bn2v);
}

// round 11
// speedup vs baseline: 2.6259x; 1.0294x over previous
#include <cuda_runtime.h>
#include <cuda_bf16.h>
#include <cstdint>

// Problem dims
#define BB    32
#define NNODE 512
#define FIN   256
#define HID   512
#define OUTC  512
#define NHEAD 4
#define DH    128
#define EPSV  1e-5f

#define KC    32          // k elements per smem stage
#define BUFSZ 32768       // AH|AL|BH|BL planes of 8KB each
#define NSTAGE 3

// ---------------- pre-split bf16 hi/lo planes (device globals) -------------
#define NX   ((size_t)16384 * 256)
#define NADJ ((size_t)512 * 512)
#define NGW  ((size_t)512 * 256)
#define NGAT ((size_t)512 * 512)
#define NCW  ((size_t)3 * 512 * 512)
#define SNO  ((size_t)512 * 512)          // 262144

__device__ __align__(16) __nv_bfloat16 g_xph[NX],   g_xpl[NX];
__device__ __align__(16) __nv_bfloat16 g_adjh[NADJ], g_adjl[NADJ];
__device__ __align__(16) __nv_bfloat16 g_gwth[NGW], g_gwtl[NGW];      // gc_w^T [512][256]
__device__ __align__(16) __nv_bfloat16 g_gath[NGAT], g_gatl[NGAT];    // gat_w [512][512]
__device__ __align__(16) __nv_bfloat16 g_cwh[NCW],  g_cwl[NCW];       // [kpos][co][ci]
__device__ __align__(16) __nv_bfloat16 g_suth[(size_t)512 * 16384], g_sutl[(size_t)512 * 16384];
__device__ __align__(16) __nv_bfloat16 g_gh[(size_t)BB * SNO],  g_gl[(size_t)BB * SNO];
__device__ __align__(16) __nv_bfloat16 g_hhh[(size_t)BB * SNO], g_hhl[(size_t)BB * SNO];
__device__ __align__(16) __nv_bfloat16 g_hth[(size_t)BB * SNO], g_htl[(size_t)BB * SNO];  // hh^T
__device__ __align__(16) __nv_bfloat16 g_ath[(size_t)128 * SNO], g_atl[(size_t)128 * SNO];
__device__ __align__(16) __nv_bfloat16 g_oh[(size_t)BB * SNO],  g_ol[(size_t)BB * SNO];
__device__ float g_att[(size_t)128 * SNO];    // fp32 logits

// ---------------------------------------------------------------------------
__device__ __forceinline__ void mma16816(float* c, const uint32_t* a, const uint32_t* b) {
    asm volatile(
        "mma.sync.aligned.m16n8k16.row.col.f32.bf16.bf16.f32 "
        "{%0,%1,%2,%3}, {%4,%5,%6,%7}, {%8,%9}, {%0,%1,%2,%3};"
        : "+f"(c[0]), "+f"(c[1]), "+f"(c[2]), "+f"(c[3])
        : "r"(a[0]), "r"(a[1]), "r"(a[2]), "r"(a[3]), "r"(b[0]), "r"(b[1]));
}
__device__ __forceinline__ void split_bf16(float x, __nv_bfloat16& h, __nv_bfloat16& l) {
    h = __float2bfloat16_rn(x);
    l = __float2bfloat16_rn(x - __bfloat162float(h));
}
__device__ __forceinline__ uint32_t sw_off(int row, int chunk) {
    return (uint32_t)((row << 6) + (((chunk) ^ ((row >> 1) & 3)) << 4));
}
__device__ __forceinline__ void ldm_x4(uint32_t& r0, uint32_t& r1, uint32_t& r2, uint32_t& r3,
                                       uint32_t a) {
    asm volatile("ldmatrix.sync.aligned.m8n8.x4.shared.b16 {%0,%1,%2,%3}, [%4];"
                 : "=r"(r0), "=r"(r1), "=r"(r2), "=r"(r3) : "r"(a));
}
__device__ __forceinline__ void cp16(uint32_t dst, const void* src, int sz) {
    asm volatile("cp.async.cg.shared.global [%0], [%1], 16, %2;"
                 :: "r"(dst), "l"(src), "r"(sz) : "memory");
}
__device__ __forceinline__ void cp_commit() {
    asm volatile("cp.async.commit_group;" ::: "memory");
}
template <int N>
__device__ __forceinline__ void cp_wait() {
    asm volatile("cp.async.wait_group %0;" :: "n"(N) : "memory");
}

#define TSTRIDE 136   // stash row stride in bf16 elems (272B, 16B-aligned)

// ---------------------------------------------------------------------------
// Pre-split GEMM, 3-stage cp.async ring, ONE barrier/step. C = A @ B^T.
// CONV: A rows shifted by (kpos-1), zero-padded; B +shift*SNO; 48 K-steps.
// EPI: 0 none, 1 (v+bias-m)*s+b then ReLU, 2 LeakyReLU(0.2)
// OUT: 0 = split bf16 planes, 1 = fp32, 2 = split planes + TRANSPOSED planes
// ---------------------------------------------------------------------------
template <int EPI, int OUT, bool CONV>
__global__ void __launch_bounds__(256, 2) gemm_p(
    const __nv_bfloat16* __restrict__ Ah, const __nv_bfloat16* __restrict__ Al,
    int lda, long sA1, long sA2,
    const __nv_bfloat16* __restrict__ Bh, const __nv_bfloat16* __restrict__ Bl,
    int ldb, long sB1, long sB2,
    float* __restrict__ Cf, __nv_bfloat16* __restrict__ Ch, __nv_bfloat16* __restrict__ Cl,
    int ldc, long sC1, long sC2,
    int K, int zdiv,
    const float* __restrict__ bias,
    const float* __restrict__ bng, const float* __restrict__ bnb,
    const float* __restrict__ bnm, const float* __restrict__ bnv,
    __nv_bfloat16* __restrict__ Th, __nv_bfloat16* __restrict__ Tl, int ldt, long sT1, long sT2)
{
    __shared__ __align__(16) unsigned char sm[NSTAGE * BUFSZ];
    const uint32_t smb = (uint32_t)__cvta_generic_to_shared(sm);

    const int z  = blockIdx.z;
    const int z1 = z / zdiv;
    const int z2 = z - z1 * zdiv;
    Ah += z1 * sA1 + z2 * sA2;  Al += z1 * sA1 + z2 * sA2;
    Bh += z1 * sB1 + z2 * sB2;  Bl += z1 * sB1 + z2 * sB2;
    if (OUT == 1) Cf += z1 * sC1 + z2 * sC2;
    else { Ch += z1 * sC1 + z2 * sC2; Cl += z1 * sC1 + z2 * sC2; }
    if (OUT == 2) { Th += z1 * sT1 + z2 * sT2; Tl += z1 * sT1 + z2 * sT2; }

    const int m0 = blockIdx.y * 128;
    const int n0 = blockIdx.x * 128;
    const int tid = threadIdx.x;

    const int w    = tid >> 5;
    const int lane = tid & 31;
    const int gq   = lane >> 2;
    const int tig  = lane & 3;
    const int wm   = (w >> 1) * 32;
    const int wn   = (w & 1) * 64;

    float acc[2][8][4];
#pragma unroll
    for (int i = 0; i < 2; i++)
#pragma unroll
        for (int j = 0; j < 8; j++)
#pragma unroll
            for (int q = 0; q < 4; q++) acc[i][j][q] = 0.f;

    const int steps = CONV ? 48 : (K >> 5);

    auto stageAsync = [&](int s, uint32_t bufo) {
        int k0, shift;
        if (CONV) { shift = s >> 4; k0 = (s & 15) * KC; }
        else      { shift = 0;      k0 = s * KC; }
        const uint32_t base = smb + bufo;
#pragma unroll
        for (int rep = 0; rep < 2; rep++) {
            const int c   = tid + rep * 256;
            const int row = c >> 2;
            const int kc  = c & 3;
            const uint32_t off = sw_off(row, kc);
            {
                long arow = m0 + row;
                int sz = 16;
                if (CONV) {
                    int rs = m0 + row + shift - 1;
                    if (rs < 0 || rs >= NNODE) { sz = 0; rs = 0; }
                    arow = rs;
                }
                const long so = arow * (long)lda + k0 + kc * 8;
                cp16(base + off,        Ah + so, sz);
                cp16(base + 8192 + off, Al + so, sz);
            }
            {
                const long so = (CONV ? (long)shift * (long)SNO : 0L)
                              + (long)(n0 + row) * (long)ldb + k0 + kc * 8;
                cp16(base + 16384 + off, Bh + so, 16);
                cp16(base + 24576 + off, Bl + so, 16);
            }
        }
    };

    auto compute = [&](uint32_t bufo) {
        const uint32_t AHs = smb + bufo, ALs = AHs + 8192;
        const uint32_t BHs = AHs + 16384, BLs = AHs + 24576;
#pragma unroll
        for (int ks = 0; ks < 2; ks++) {
            const int kc = ks * 2;
            uint32_t afh[2][4], afl[2][4];
            const int arow = wm + (lane & 15);
            const int achk = kc + (lane >> 4);
#pragma unroll
            for (int mt = 0; mt < 2; mt++) {
                const uint32_t off = sw_off(arow + mt * 16, achk);
                ldm_x4(afh[mt][0], afh[mt][1], afh[mt][2], afh[mt][3], AHs + off);
                ldm_x4(afl[mt][0], afl[mt][1], afl[mt][2], afl[mt][3], ALs + off);
            }
            const int brow_b = wn + (lane & 7) + ((lane >> 4) << 3);
            const int bchk = kc + ((lane >> 3) & 1);
#pragma unroll
            for (int ntp = 0; ntp < 4; ntp++) {
                const uint32_t off = sw_off(brow_b + ntp * 16, bchk);
                uint32_t bh[4], bl[4];
                ldm_x4(bh[0], bh[1], bh[2], bh[3], BHs + off);
                ldm_x4(bl[0], bl[1], bl[2], bl[3], BLs + off);
#pragma unroll
                for (int hf = 0; hf < 2; hf++) {
                    const int nt = ntp * 2 + hf;
                    uint32_t bfh[2] = {bh[hf * 2], bh[hf * 2 + 1]};
                    uint32_t bfl[2] = {bl[hf * 2], bl[hf * 2 + 1]};
#pragma unroll
                    for (int mt = 0; mt < 2; mt++) {
                        mma16816(acc[mt][nt], afh[mt], bfh);
                        mma16816(acc[mt][nt], afh[mt], bfl);
                        mma16816(acc[mt][nt], afl[mt], bfh);
                    }
                }
            }
        }
    };

    // ---- 3-stage ring, one barrier per step ----
    stageAsync(0, 0); cp_commit();
    stageAsync(1, BUFSZ); cp_commit();
    for (int s = 0; s < steps; s++) {
        cp_wait<1>();          // group for buffer s complete
        __syncthreads();       // make all threads' cp.async visible
        compute((uint32_t)(s % NSTAGE) * BUFSZ);
        if (s + 2 < steps) stageAsync(s + 2, (uint32_t)((s + 2) % NSTAGE) * BUFSZ);
        cp_commit();
    }

    // ---- epilogue ----
    __nv_bfloat16* sth = reinterpret_cast<__nv_bfloat16*>(sm);
    __nv_bfloat16* stl = reinterpret_cast<__nv_bfloat16*>(sm + 128 * TSTRIDE * 2);
    if (OUT == 2) __syncthreads();   // mainloop smem reads done before stash reuse

#pragma unroll
    for (int mt = 0; mt < 2; mt++) {
        const long r0 = m0 + wm + mt * 16 + gq;
        const long r1 = r0 + 8;
#pragma unroll
        for (int nt = 0; nt < 8; nt++) {
            const int cb = n0 + wn + nt * 8 + 2 * tig;
            float v[4] = {acc[mt][nt][0], acc[mt][nt][1], acc[mt][nt][2], acc[mt][nt][3]};
            if (EPI == 1) {
#pragma unroll
                for (int q = 0; q < 4; q++) {
                    const int n = cb + (q & 1);
                    float sc = bng[n] * rsqrtf(bnv[n] + EPSV);
                    v[q] = (v[q] + bias[n] - bnm[n]) * sc + bnb[n];
                    v[q] = fmaxf(v[q], 0.f);
                }
            } else if (EPI == 2) {
#pragma unroll
                for (int q = 0; q < 4; q++) v[q] = (v[q] > 0.f) ? v[q] : 0.2f * v[q];
            }
            if (OUT == 1) {
                *reinterpret_cast<float2*>(Cf + r0 * ldc + cb) = make_float2(v[0], v[1]);
                *reinterpret_cast<float2*>(Cf + r1 * ldc + cb) = make_float2(v[2], v[3]);
            } else {
                __nv_bfloat16 h0, l0, h1, l1, h2, l2, h3, l3;
                split_bf16(v[0], h0, l0); split_bf16(v[1], h1, l1);
                split_bf16(v[2], h2, l2); split_bf16(v[3], h3, l3);
                __nv_bfloat162 ph, pl;
                ph.x = h0; ph.y = h1; pl.x = l0; pl.y = l1;
                *reinterpret_cast<__nv_bfloat162*>(Ch + r0 * ldc + cb) = ph;
                *reinterpret_cast<__nv_bfloat162*>(Cl + r0 * ldc + cb) = pl;
                ph.x = h2; ph.y = h3; pl.x = l2; pl.y = l3;
                *reinterpret_cast<__nv_bfloat162*>(Ch + r1 * ldc + cb) = ph;
                *reinterpret_cast<__nv_bfloat162*>(Cl + r1 * ldc + cb) = pl;
                if (OUT == 2) {
                    const int lr0 = (int)(r0 - m0), lr1 = (int)(r1 - m0);
                    const int lc = cb - n0;
                    sth[(lc + 0) * TSTRIDE + lr0] = h0;
                    sth[(lc + 1) * TSTRIDE + lr0] = h1;
                    sth[(lc + 0) * TSTRIDE + lr1] = h2;
                    sth[(lc + 1) * TSTRIDE + lr1] = h3;
                    stl[(lc + 0) * TSTRIDE + lr0] = l0;
                    stl[(lc + 1) * TSTRIDE + lr0] = l1;
                    stl[(lc + 0) * TSTRIDE + lr1] = l2;
                    stl[(lc + 1) * TSTRIDE + lr1] = l3;
                }
            }
        }
    }

    if (OUT == 2) {
        __syncthreads();
        const int col  = tid >> 1;       // 0..127 (C column = T row)
        const int half = tid & 1;        // m-half
        const long trow = (long)(n0 + col) * ldt + m0 + half * 64;
#pragma unroll
        for (int i = 0; i < 8; i++) {
            *reinterpret_cast<uint4*>(Th + trow + i * 8) =
                *reinterpret_cast<const uint4*>(&sth[col * TSTRIDE + half * 64 + i * 8]);
            *reinterpret_cast<uint4*>(Tl + trow + i * 8) =
                *reinterpret_cast<const uint4*>(&stl[col * TSTRIDE + half * 64 + i * 8]);
        }
    }
}

// ---------------------------------------------------------------------------
// prep: split raw fp32 inputs into bf16 hi/lo planes (with needed transposes)
// ---------------------------------------------------------------------------
__global__ void prep(const float* __restrict__ x, const float* __restrict__ adj,
                     const float* __restrict__ gc_w, const float* __restrict__ gat_w,
                     const float* __restrict__ conv_w)
{
    long i = (long)blockIdx.x * 256 + threadIdx.x;
    float v; __nv_bfloat16 h, l;
    if (i < (long)NX) {
        v = x[i]; split_bf16(v, h, l); g_xph[i] = h; g_xpl[i] = l; return;
    }
    i -= NX;
    if (i < (long)NADJ) {
        v = adj[i]; split_bf16(v, h, l); g_adjh[i] = h; g_adjl[i] = l; return;
    }
    i -= NADJ;
    if (i < (long)NGW) {       // gwt[d][c] = gc_w[c][d]
        long d = i >> 8, c = i & 255;
        v = gc_w[c * 512 + d]; split_bf16(v, h, l); g_gwth[i] = h; g_gwtl[i] = l; return;
    }
    i -= NGW;
    if (i < (long)NGAT) {
        v = gat_w[i]; split_bf16(v, h, l); g_gath[i] = h; g_gatl[i] = l; return;
    }
    i -= NGAT;
    if (i < (long)NCW) {       // cw[kpos][co][ci] = conv_w[co][ci][kpos]
        long kpos = i / 262144, r = i % 262144;
        long co = r >> 9, ci = r & 511;
        v = conv_w[co * 1536 + ci * 3 + kpos];
        split_bf16(v, h, l); g_cwh[i] = h; g_cwl[i] = l; return;
    }
}

// ---------------------------------------------------------------------------
// Row softmax over 512 fp32 -> split bf16 planes
// ---------------------------------------------------------------------------
__global__ void softmax512(const float* __restrict__ att,
                           __nv_bfloat16* __restrict__ oh, __nv_bfloat16* __restrict__ ol)
{
    __shared__ float red[256];
    const long row = blockIdx.x;
    const float* p = att + row * 512;
    const int t = threadIdx.x;
    float a = p[t];
    float b = p[t + 256];
    red[t] = fmaxf(a, b);
    __syncthreads();
    for (int s = 128; s > 0; s >>= 1) {
        if (t < s) red[t] = fmaxf(red[t], red[t + s]);
        __syncthreads();
    }
    const float m = red[0];
    __syncthreads();
    float e0 = __expf(a - m);
    float e1 = __expf(b - m);
    red[t] = e0 + e1;
    __syncthreads();
    for (int s = 128; s > 0; s >>= 1) {
        if (t < s) red[t] += red[t + s];
        __syncthreads();
    }
    const float inv = 1.f / red[0];
    __nv_bfloat16 h, l;
    split_bf16(e0 * inv, h, l);
    oh[row * 512 + t] = h; ol[row * 512 + t] = l;
    split_bf16(e1 * inv, h, l);
    oh[row * 512 + t + 256] = h; ol[row * 512 + t + 256] = l;
}

// ---------------------------------------------------------------------------
extern "C" void kernel_launch(void* const* d_in, const int* in_sizes, int n_in,
                              void* d_out, int out_size)
{
    const float* x      = (const float*)d_in[0];
    const float* adj    = (const float*)d_in[1];
    const float* gc_w   = (const float*)d_in[2];
    const float* gc_b   = (const float*)d_in[3];
    const float* bn1g   = (const float*)d_in[4];
    const float* bn1b   = (const float*)d_in[5];
    const float* bn1m   = (const float*)d_in[6];
    const float* bn1v   = (const float*)d_in[7];
    const float* gat_w  = (const float*)d_in[8];
    const float* conv_w = (const float*)d_in[9];
    const float* conv_b = (const float*)d_in[10];
    const float* bn2g   = (const float*)d_in[11];
    const float* bn2b   = (const float*)d_in[12];
    const float* bn2m   = (const float*)d_in[13];
    const float* bn2v   = (const float*)d_in[14];
    float* out = (float*)d_out;

    __nv_bfloat16 *xph, *xpl, *adjh, *adjl, *gwth, *gwtl, *gath, *gatl, *cwh, *cwl;
    __nv_bfloat16 *suth, *sutl, *gh, *gl, *hhh, *hhl, *hth, *htl, *ath, *atl, *oh, *ol;
    float* att;
    cudaGetSymbolAddress((void**)&xph, g_xph);   cudaGetSymbolAddress((void**)&xpl, g_xpl);
    cudaGetSymbolAddress((void**)&adjh, g_adjh); cudaGetSymbolAddress((void**)&adjl, g_adjl);
    cudaGetSymbolAddress((void**)&gwth, g_gwth); cudaGetSymbolAddress((void**)&gwtl, g_gwtl);
    cudaGetSymbolAddress((void**)&gath, g_gath); cudaGetSymbolAddress((void**)&gatl, g_gatl);
    cudaGetSymbolAddress((void**)&cwh, g_cwh);   cudaGetSymbolAddress((void**)&cwl, g_cwl);
    cudaGetSymbolAddress((void**)&suth, g_suth); cudaGetSymbolAddress((void**)&sutl, g_sutl);
    cudaGetSymbolAddress((void**)&gh, g_gh);     cudaGetSymbolAddress((void**)&gl, g_gl);
    cudaGetSymbolAddress((void**)&hhh, g_hhh);   cudaGetSymbolAddress((void**)&hhl, g_hhl);
    cudaGetSymbolAddress((void**)&hth, g_hth);   cudaGetSymbolAddress((void**)&htl, g_htl);
    cudaGetSymbolAddress((void**)&ath, g_ath);   cudaGetSymbolAddress((void**)&atl, g_atl);
    cudaGetSymbolAddress((void**)&oh, g_oh);     cudaGetSymbolAddress((void**)&ol, g_ol);
    cudaGetSymbolAddress((void**)&att, g_att);

    const long total_prep = (long)(NX + NADJ + NGW + NGAT + NCW);

    // 0) split inputs
    prep<<<(unsigned)((total_prep + 255) / 256), 256>>>(x, adj, gc_w, gat_w, conv_w);

    // 1) supT[d][bn] = sum_c gwt[d][c] * x[bn][c]
    gemm_p<0, 0, false><<<dim3(128, 4, 1), 256>>>(
        gwth, gwtl, 256, 0, 0,
        xph, xpl, 256, 0, 0,
        nullptr, suth, sutl, 16384, 0, 0,
        256, 1, nullptr, nullptr, nullptr, nullptr, nullptr,
        nullptr, nullptr, 0, 0, 0);

    // 2) g[b] = relu(bn1(adj @ sup + gc_b))
    gemm_p<1, 0, false><<<dim3(4, 4, BB), 256>>>(
        adjh, adjl, 512, 0, 0,
        suth, sutl, 16384, 512, 0,
        nullptr, gh, gl, 512, (long)SNO, 0,
        512, 1, gc_b, bn1g, bn1b, bn1m, bn1v,
        nullptr, nullptr, 0, 0, 0);

    // 3) hh[b] = g @ gat_w^T   (+ fused transpose -> hhT)
    gemm_p<0, 2, false><<<dim3(4, 4, BB), 256>>>(
        gh, gl, 512, (long)SNO, 0,
        gath, gatl, 512, 0, 0,
        nullptr, hhh, hhl, 512, (long)SNO, 0,
        512, 1, nullptr, nullptr, nullptr, nullptr, nullptr,
        hth, htl, 512, (long)SNO, 0);

    // 4) logits[b,h] = leaky(hh_h @ hh_h^T)
    gemm_p<2, 1, false><<<dim3(4, 4, BB * NHEAD), 256>>>(
        hhh, hhl, 512, (long)SNO, 128,
        hhh, hhl, 512, (long)SNO, 128,
        att, nullptr, nullptr, 512, (long)(4 * SNO), (long)SNO,
        128, NHEAD, nullptr, nullptr, nullptr, nullptr, nullptr,
        nullptr, nullptr, 0, 0, 0);

    // 5) softmax -> split att planes
    softmax512<<<128 * 512, 256>>>(att, ath, atl);

    // 6) o[b,h] = att @ hh_h
    gemm_p<0, 0, false><<<dim3(1, 4, BB * NHEAD), 256>>>(
        ath, atl, 512, (long)(4 * SNO), (long)SNO,
        hth, htl, 512, (long)SNO, (long)(128 * 512),
        nullptr, oh, ol, 512, (long)SNO, 128,
        512, NHEAD, nullptr, nullptr, nullptr, nullptr, nullptr,
        nullptr, nullptr, 0, 0, 0);

    // 7) conv1d(k=3,p=1) + bias + bn2 + relu -> out fp32
    gemm_p<1, 1, true><<<dim3(4, 4, BB), 256>>>(
        oh, ol, 512, (long)SNO, 0,
        cwh, cwl, 512, 0, 0,
        out, nullptr, nullptr, 512, (long)SNO, 0,
        3 * 512, 1, conv_b, bn2g, bn2b, bn2m, bn2v,
        nullptr, nullptr, 0, 0, 0);
}

// round 13
// speedup vs baseline: 2.7452x; 1.0455x over previous
#include <cuda_runtime.h>
#include <cuda_bf16.h>
#include <cstdint>

// Problem dims
#define BB    32
#define NNODE 512
#define FIN   256
#define HID   512
#define OUTC  512
#define NHEAD 4
#define DH    128
#define EPSV  1e-5f

#define KC    32          // k elements per smem stage
#define BUFSZ 32768       // AH|AL|BH|BL planes of 8KB each
#define NSTAGE 3

// ---------------- pre-split bf16 hi/lo planes (device globals) -------------
#define NX   ((size_t)16384 * 256)
#define NADJ ((size_t)512 * 512)
#define NGW  ((size_t)512 * 256)
#define NGAT ((size_t)512 * 512)
#define NCW  ((size_t)3 * 512 * 512)
#define SNO  ((size_t)512 * 512)          // 262144

__device__ __align__(16) __nv_bfloat16 g_xph[NX],   g_xpl[NX];
__device__ __align__(16) __nv_bfloat16 g_adjh[NADJ], g_adjl[NADJ];
__device__ __align__(16) __nv_bfloat16 g_gwth[NGW], g_gwtl[NGW];      // gc_w^T [512][256]
__device__ __align__(16) __nv_bfloat16 g_gath[NGAT], g_gatl[NGAT];    // gat_w [512][512]
__device__ __align__(16) __nv_bfloat16 g_cwh[NCW],  g_cwl[NCW];       // [kpos][co][ci]
__device__ __align__(16) __nv_bfloat16 g_suth[(size_t)512 * 16384], g_sutl[(size_t)512 * 16384];
__device__ __align__(16) __nv_bfloat16 g_gh[(size_t)BB * SNO],  g_gl[(size_t)BB * SNO];
__device__ __align__(16) __nv_bfloat16 g_hhh[(size_t)BB * SNO], g_hhl[(size_t)BB * SNO];
__device__ __align__(16) __nv_bfloat16 g_hth[(size_t)BB * SNO], g_htl[(size_t)BB * SNO];  // hh^T
__device__ __align__(16) __nv_bfloat16 g_ath[(size_t)128 * SNO], g_atl[(size_t)128 * SNO];
__device__ __align__(16) __nv_bfloat16 g_oh[(size_t)BB * SNO],  g_ol[(size_t)BB * SNO];
__device__ float g_att[(size_t)128 * SNO];    // fp32 logits

// ---------------------------------------------------------------------------
__device__ __forceinline__ void mma16816(float* c, const uint32_t* a, const uint32_t* b) {
    asm volatile(
        "mma.sync.aligned.m16n8k16.row.col.f32.bf16.bf16.f32 "
        "{%0,%1,%2,%3}, {%4,%5,%6,%7}, {%8,%9}, {%0,%1,%2,%3};"
        : "+f"(c[0]), "+f"(c[1]), "+f"(c[2]), "+f"(c[3])
        : "r"(a[0]), "r"(a[1]), "r"(a[2]), "r"(a[3]), "r"(b[0]), "r"(b[1]));
}
__device__ __forceinline__ void split_bf16(float x, __nv_bfloat16& h, __nv_bfloat16& l) {
    h = __float2bfloat16_rn(x);
    l = __float2bfloat16_rn(x - __bfloat162float(h));
}
__device__ __forceinline__ uint32_t sw_off(int row, int chunk) {
    return (uint32_t)((row << 6) + (((chunk) ^ ((row >> 1) & 3)) << 4));
}
__device__ __forceinline__ void ldm_x4(uint32_t& r0, uint32_t& r1, uint32_t& r2, uint32_t& r3,
                                       uint32_t a) {
    asm volatile("ldmatrix.sync.aligned.m8n8.x4.shared.b16 {%0,%1,%2,%3}, [%4];"
                 : "=r"(r0), "=r"(r1), "=r"(r2), "=r"(r3) : "r"(a));
}
__device__ __forceinline__ void cp16(uint32_t dst, const void* src, int sz) {
    asm volatile("cp.async.cg.shared.global [%0], [%1], 16, %2;"
                 :: "r"(dst), "l"(src), "r"(sz) : "memory");
}
__device__ __forceinline__ void cp_commit() {
    asm volatile("cp.async.commit_group;" ::: "memory");
}
template <int N>
__device__ __forceinline__ void cp_wait() {
    asm volatile("cp.async.wait_group %0;" :: "n"(N) : "memory");
}

#define TSTRIDE 136   // stash row stride in bf16 elems (272B, 16B-aligned)

// ---------------------------------------------------------------------------
// Pre-split GEMM, 3-stage cp.async ring, ONE barrier/step, prefetch-first.
// C = A @ B^T.  CONV: A rows shifted by (kpos-1), zero-padded; B +shift*SNO.
// EPI: 0 none, 1 (v+bias-m)*s+b then ReLU, 2 LeakyReLU(0.2)
// OUT: 0 = split bf16 planes, 1 = fp32, 2 = split planes + TRANSPOSED planes
// ---------------------------------------------------------------------------
template <int EPI, int OUT, bool CONV>
__global__ void __launch_bounds__(256, 2) gemm_p(
    const __nv_bfloat16* __restrict__ Ah, const __nv_bfloat16* __restrict__ Al,
    int lda, long sA1, long sA2,
    const __nv_bfloat16* __restrict__ Bh, const __nv_bfloat16* __restrict__ Bl,
    int ldb, long sB1, long sB2,
    float* __restrict__ Cf, __nv_bfloat16* __restrict__ Ch, __nv_bfloat16* __restrict__ Cl,
    int ldc, long sC1, long sC2,
    int K, int zdiv,
    const float* __restrict__ bias,
    const float* __restrict__ bng, const float* __restrict__ bnb,
    const float* __restrict__ bnm, const float* __restrict__ bnv,
    __nv_bfloat16* __restrict__ Th, __nv_bfloat16* __restrict__ Tl, int ldt, long sT1, long sT2)
{
    __shared__ __align__(16) unsigned char sm[NSTAGE * BUFSZ];
    const uint32_t smb = (uint32_t)__cvta_generic_to_shared(sm);

    const int z  = blockIdx.z;
    const int z1 = z / zdiv;
    const int z2 = z - z1 * zdiv;
    Ah += z1 * sA1 + z2 * sA2;  Al += z1 * sA1 + z2 * sA2;
    Bh += z1 * sB1 + z2 * sB2;  Bl += z1 * sB1 + z2 * sB2;
    if (OUT == 1) Cf += z1 * sC1 + z2 * sC2;
    else { Ch += z1 * sC1 + z2 * sC2; Cl += z1 * sC1 + z2 * sC2; }
    if (OUT == 2) { Th += z1 * sT1 + z2 * sT2; Tl += z1 * sT1 + z2 * sT2; }

    const int m0 = blockIdx.y * 128;
    const int n0 = blockIdx.x * 128;
    const int tid = threadIdx.x;

    const int w    = tid >> 5;
    const int lane = tid & 31;
    const int gq   = lane >> 2;
    const int tig  = lane & 3;
    const int wm   = (w >> 1) * 32;
    const int wn   = (w & 1) * 64;

    float acc[2][8][4];
#pragma unroll
    for (int i = 0; i < 2; i++)
#pragma unroll
        for (int j = 0; j < 8; j++)
#pragma unroll
            for (int q = 0; q < 4; q++) acc[i][j][q] = 0.f;

    const int steps = CONV ? 48 : (K >> 5);

    auto stageAsync = [&](int s, uint32_t bufo) {
        int k0, shift;
        if (CONV) { shift = s >> 4; k0 = (s & 15) * KC; }
        else      { shift = 0;      k0 = s * KC; }
        const uint32_t base = smb + bufo;
#pragma unroll
        for (int rep = 0; rep < 2; rep++) {
            const int c   = tid + rep * 256;
            const int row = c >> 2;
            const int kc  = c & 3;
            const uint32_t off = sw_off(row, kc);
            {
                long arow = m0 + row;
                int sz = 16;
                if (CONV) {
                    int rs = m0 + row + shift - 1;
                    if (rs < 0 || rs >= NNODE) { sz = 0; rs = 0; }
                    arow = rs;
                }
                const long so = arow * (long)lda + k0 + kc * 8;
                cp16(base + off,        Ah + so, sz);
                cp16(base + 8192 + off, Al + so, sz);
            }
            {
                const long so = (CONV ? (long)shift * (long)SNO : 0L)
                              + (long)(n0 + row) * (long)ldb + k0 + kc * 8;
                cp16(base + 16384 + off, Bh + so, 16);
                cp16(base + 24576 + off, Bl + so, 16);
            }
        }
    };

    auto compute = [&](uint32_t bufo) {
        const uint32_t AHs = smb + bufo, ALs = AHs + 8192;
        const uint32_t BHs = AHs + 16384, BLs = AHs + 24576;
#pragma unroll
        for (int ks = 0; ks < 2; ks++) {
            const int kc = ks * 2;
            uint32_t afh[2][4], afl[2][4];
            const int arow = wm + (lane & 15);
            const int achk = kc + (lane >> 4);
#pragma unroll
            for (int mt = 0; mt < 2; mt++) {
                const uint32_t off = sw_off(arow + mt * 16, achk);
                ldm_x4(afh[mt][0], afh[mt][1], afh[mt][2], afh[mt][3], AHs + off);
                ldm_x4(afl[mt][0], afl[mt][1], afl[mt][2], afl[mt][3], ALs + off);
            }
            const int brow_b = wn + (lane & 7) + ((lane >> 4) << 3);
            const int bchk = kc + ((lane >> 3) & 1);
#pragma unroll
            for (int ntp = 0; ntp < 4; ntp++) {
                const uint32_t off = sw_off(brow_b + ntp * 16, bchk);
                uint32_t bh[4], bl[4];
                ldm_x4(bh[0], bh[1], bh[2], bh[3], BHs + off);
                ldm_x4(bl[0], bl[1], bl[2], bl[3], BLs + off);
#pragma unroll
                for (int hf = 0; hf < 2; hf++) {
                    const int nt = ntp * 2 + hf;
                    uint32_t bfh[2] = {bh[hf * 2], bh[hf * 2 + 1]};
                    uint32_t bfl[2] = {bl[hf * 2], bl[hf * 2 + 1]};
#pragma unroll
                    for (int mt = 0; mt < 2; mt++) {
                        mma16816(acc[mt][nt], afh[mt], bfh);
                        mma16816(acc[mt][nt], afh[mt], bfl);
                        mma16816(acc[mt][nt], afl[mt], bfh);
                    }
                }
            }
        }
    };

    // ---- 3-stage ring, one barrier per step, PREFETCH BEFORE COMPUTE ----
    // Group id s is committed before compute(s-2) runs -> every group has
    // ~2 compute-phases of latency cover when waited.
    stageAsync(0, 0); cp_commit();
    stageAsync(1, BUFSZ); cp_commit();
    for (int s = 0; s < steps; s++) {
        cp_wait<1>();          // group s complete (s+1 may be pending)
        __syncthreads();       // visibility + buffer (s+2)%3 free (read at s-1)
        if (s + 2 < steps) stageAsync(s + 2, (uint32_t)((s + 2) % NSTAGE) * BUFSZ);
        cp_commit();           // unconditional: keeps group count == s+2
        compute((uint32_t)(s % NSTAGE) * BUFSZ);
    }

    // ---- epilogue ----
    __nv_bfloat16* sth = reinterpret_cast<__nv_bfloat16*>(sm);
    __nv_bfloat16* stl = reinterpret_cast<__nv_bfloat16*>(sm + 128 * TSTRIDE * 2);
    if (OUT == 2) __syncthreads();   // mainloop smem reads done before stash reuse

#pragma unroll
    for (int mt = 0; mt < 2; mt++) {
        const long r0 = m0 + wm + mt * 16 + gq;
        const long r1 = r0 + 8;
#pragma unroll
        for (int nt = 0; nt < 8; nt++) {
            const int cb = n0 + wn + nt * 8 + 2 * tig;
            float v[4] = {acc[mt][nt][0], acc[mt][nt][1], acc[mt][nt][2], acc[mt][nt][3]};
            if (EPI == 1) {
#pragma unroll
                for (int q = 0; q < 4; q++) {
                    const int n = cb + (q & 1);
                    float sc = bng[n] * rsqrtf(bnv[n] + EPSV);
                    v[q] = (v[q] + bias[n] - bnm[n]) * sc + bnb[n];
                    v[q] = fmaxf(v[q], 0.f);
                }
            } else if (EPI == 2) {
#pragma unroll
                for (int q = 0; q < 4; q++) v[q] = (v[q] > 0.f) ? v[q] : 0.2f * v[q];
            }
            if (OUT == 1) {
                *reinterpret_cast<float2*>(Cf + r0 * ldc + cb) = make_float2(v[0], v[1]);
                *reinterpret_cast<float2*>(Cf + r1 * ldc + cb) = make_float2(v[2], v[3]);
            } else {
                __nv_bfloat16 h0, l0, h1, l1, h2, l2, h3, l3;
                split_bf16(v[0], h0, l0); split_bf16(v[1], h1, l1);
                split_bf16(v[2], h2, l2); split_bf16(v[3], h3, l3);
                __nv_bfloat162 ph, pl;
                ph.x = h0; ph.y = h1; pl.x = l0; pl.y = l1;
                *reinterpret_cast<__nv_bfloat162*>(Ch + r0 * ldc + cb) = ph;
                *reinterpret_cast<__nv_bfloat162*>(Cl + r0 * ldc + cb) = pl;
                ph.x = h2; ph.y = h3; pl.x = l2; pl.y = l3;
                *reinterpret_cast<__nv_bfloat162*>(Ch + r1 * ldc + cb) = ph;
                *reinterpret_cast<__nv_bfloat162*>(Cl + r1 * ldc + cb) = pl;
                if (OUT == 2) {
                    const int lr0 = (int)(r0 - m0), lr1 = (int)(r1 - m0);
                    const int lc = cb - n0;
                    sth[(lc + 0) * TSTRIDE + lr0] = h0;
                    sth[(lc + 1) * TSTRIDE + lr0] = h1;
                    sth[(lc + 0) * TSTRIDE + lr1] = h2;
                    sth[(lc + 1) * TSTRIDE + lr1] = h3;
                    stl[(lc + 0) * TSTRIDE + lr0] = l0;
                    stl[(lc + 1) * TSTRIDE + lr0] = l1;
                    stl[(lc + 0) * TSTRIDE + lr1] = l2;
                    stl[(lc + 1) * TSTRIDE + lr1] = l3;
                }
            }
        }
    }

    if (OUT == 2) {
        __syncthreads();
        const int col  = tid >> 1;       // 0..127 (C column = T row)
        const int half = tid & 1;        // m-half
        const long trow = (long)(n0 + col) * ldt + m0 + half * 64;
#pragma unroll
        for (int i = 0; i < 8; i++) {
            *reinterpret_cast<uint4*>(Th + trow + i * 8) =
                *reinterpret_cast<const uint4*>(&sth[col * TSTRIDE + half * 64 + i * 8]);
            *reinterpret_cast<uint4*>(Tl + trow + i * 8) =
                *reinterpret_cast<const uint4*>(&stl[col * TSTRIDE + half * 64 + i * 8]);
        }
    }
}

// ---------------------------------------------------------------------------
// prep: split raw fp32 inputs into bf16 hi/lo planes (with needed transposes)
// ---------------------------------------------------------------------------
__global__ void prep(const float* __restrict__ x, const float* __restrict__ adj,
                     const float* __restrict__ gc_w, const float* __restrict__ gat_w,
                     const float* __restrict__ conv_w)
{
    long i = (long)blockIdx.x * 256 + threadIdx.x;
    float v; __nv_bfloat16 h, l;
    if (i < (long)NX) {
        v = x[i]; split_bf16(v, h, l); g_xph[i] = h; g_xpl[i] = l; return;
    }
    i -= NX;
    if (i < (long)NADJ) {
        v = adj[i]; split_bf16(v, h, l); g_adjh[i] = h; g_adjl[i] = l; return;
    }
    i -= NADJ;
    if (i < (long)NGW) {       // gwt[d][c] = gc_w[c][d]
        long d = i >> 8, c = i & 255;
        v = gc_w[c * 512 + d]; split_bf16(v, h, l); g_gwth[i] = h; g_gwtl[i] = l; return;
    }
    i -= NGW;
    if (i < (long)NGAT) {
        v = gat_w[i]; split_bf16(v, h, l); g_gath[i] = h; g_gatl[i] = l; return;
    }
    i -= NGAT;
    if (i < (long)NCW) {       // cw[kpos][co][ci] = conv_w[co][ci][kpos]
        long kpos = i / 262144, r = i % 262144;
        long co = r >> 9, ci = r & 511;
        v = conv_w[co * 1536 + ci * 3 + kpos];
        split_bf16(v, h, l); g_cwh[i] = h; g_cwl[i] = l; return;
    }
}

// ---------------------------------------------------------------------------
// Row softmax over 512 fp32 -> split bf16 planes (shuffle reductions)
// ---------------------------------------------------------------------------
__global__ void softmax512(const float* __restrict__ att,
                           __nv_bfloat16* __restrict__ oh, __nv_bfloat16* __restrict__ ol)
{
    __shared__ float wmax[8], wsum[8];
    const long row = blockIdx.x;
    const float* p = att + row * 512;
    const int t = threadIdx.x;
    const int w = t >> 5, ln = t & 31;
    float a = p[t];
    float b = p[t + 256];
    float mx = fmaxf(a, b);
#pragma unroll
    for (int o = 16; o; o >>= 1) mx = fmaxf(mx, __shfl_xor_sync(0xffffffffu, mx, o));
    if (ln == 0) wmax[w] = mx;
    __syncthreads();
    float m = fmaxf(fmaxf(fmaxf(wmax[0], wmax[1]), fmaxf(wmax[2], wmax[3])),
                    fmaxf(fmaxf(wmax[4], wmax[5]), fmaxf(wmax[6], wmax[7])));
    float e0 = __expf(a - m);
    float e1 = __expf(b - m);
    float sm = e0 + e1;
#pragma unroll
    for (int o = 16; o; o >>= 1) sm += __shfl_xor_sync(0xffffffffu, sm, o);
    if (ln == 0) wsum[w] = sm;
    __syncthreads();
    float tot = (wsum[0] + wsum[1]) + (wsum[2] + wsum[3])
              + (wsum[4] + wsum[5]) + (wsum[6] + wsum[7]);
    const float inv = 1.f / tot;
    __nv_bfloat16 h, l;
    split_bf16(e0 * inv, h, l);
    oh[row * 512 + t] = h; ol[row * 512 + t] = l;
    split_bf16(e1 * inv, h, l);
    oh[row * 512 + t + 256] = h; ol[row * 512 + t + 256] = l;
}

// ---------------------------------------------------------------------------
extern "C" void kernel_launch(void* const* d_in, const int* in_sizes, int n_in,
                              void* d_out, int out_size)
{
    const float* x      = (const float*)d_in[0];
    const float* adj    = (const float*)d_in[1];
    const float* gc_w   = (const float*)d_in[2];
    const float* gc_b   = (const float*)d_in[3];
    const float* bn1g   = (const float*)d_in[4];
    const float* bn1b   = (const float*)d_in[5];
    const float* bn1m   = (const float*)d_in[6];
    const float* bn1v   = (const float*)d_in[7];
    const float* gat_w  = (const float*)d_in[8];
    const float* conv_w = (const float*)d_in[9];
    const float* conv_b = (const float*)d_in[10];
    const float* bn2g   = (const float*)d_in[11];
    const float* bn2b   = (const float*)d_in[12];
    const float* bn2m   = (const float*)d_in[13];
    const float* bn2v   = (const float*)d_in[14];
    float* out = (float*)d_out;

    __nv_bfloat16 *xph, *xpl, *adjh, *adjl, *gwth, *gwtl, *gath, *gatl, *cwh, *cwl;
    __nv_bfloat16 *suth, *sutl, *gh, *gl, *hhh, *hhl, *hth, *htl, *ath, *atl, *oh, *ol;
    float* att;
    cudaGetSymbolAddress((void**)&xph, g_xph);   cudaGetSymbolAddress((void**)&xpl, g_xpl);
    cudaGetSymbolAddress((void**)&adjh, g_adjh); cudaGetSymbolAddress((void**)&adjl, g_adjl);
    cudaGetSymbolAddress((void**)&gwth, g_gwth); cudaGetSymbolAddress((void**)&gwtl, g_gwtl);
    cudaGetSymbolAddress((void**)&gath, g_gath); cudaGetSymbolAddress((void**)&gatl, g_gatl);
    cudaGetSymbolAddress((void**)&cwh, g_cwh);   cudaGetSymbolAddress((void**)&cwl, g_cwl);
    cudaGetSymbolAddress((void**)&suth, g_suth); cudaGetSymbolAddress((void**)&sutl, g_sutl);
    cudaGetSymbolAddress((void**)&gh, g_gh);     cudaGetSymbolAddress((void**)&gl, g_gl);
    cudaGetSymbolAddress((void**)&hhh, g_hhh);   cudaGetSymbolAddress((void**)&hhl, g_hhl);
    cudaGetSymbolAddress((void**)&hth, g_hth);   cudaGetSymbolAddress((void**)&htl, g_htl);
    cudaGetSymbolAddress((void**)&ath, g_ath);   cudaGetSymbolAddress((void**)&atl, g_atl);
    cudaGetSymbolAddress((void**)&oh, g_oh);     cudaGetSymbolAddress((void**)&ol, g_ol);
    cudaGetSymbolAddress((void**)&att, g_att);

    const long total_prep = (long)(NX + NADJ + NGW + NGAT + NCW);

    // 0) split inputs
    prep<<<(unsigned)((total_prep + 255) / 256), 256>>>(x, adj, gc_w, gat_w, conv_w);

    // 1) supT[d][bn] = sum_c gwt[d][c] * x[bn][c]
    gemm_p<0, 0, false><<<dim3(128, 4, 1), 256>>>(
        gwth, gwtl, 256, 0, 0,
        xph, xpl, 256, 0, 0,
        nullptr, suth, sutl, 16384, 0, 0,
        256, 1, nullptr, nullptr, nullptr, nullptr, nullptr,
        nullptr, nullptr, 0, 0, 0);

    // 2) g[b] = relu(bn1(adj @ sup + gc_b))
    gemm_p<1, 0, false><<<dim3(4, 4, BB), 256>>>(
        adjh, adjl, 512, 0, 0,
        suth, sutl, 16384, 512, 0,
        nullptr, gh, gl, 512, (long)SNO, 0,
        512, 1, gc_b, bn1g, bn1b, bn1m, bn1v,
        nullptr, nullptr, 0, 0, 0);

    // 3) hh[b] = g @ gat_w^T   (+ fused transpose -> hhT)
    gemm_p<0, 2, false><<<dim3(4, 4, BB), 256>>>(
        gh, gl, 512, (long)SNO, 0,
        gath, gatl, 512, 0, 0,
        nullptr, hhh, hhl, 512, (long)SNO, 0,
        512, 1, nullptr, nullptr, nullptr, nullptr, nullptr,
        hth, htl, 512, (long)SNO, 0);

    // 4) logits[b,h] = leaky(hh_h @ hh_h^T)
    gemm_p<2, 1, false><<<dim3(4, 4, BB * NHEAD), 256>>>(
        hhh, hhl, 512, (long)SNO, 128,
        hhh, hhl, 512, (long)SNO, 128,
        att, nullptr, nullptr, 512, (long)(4 * SNO), (long)SNO,
        128, NHEAD, nullptr, nullptr, nullptr, nullptr, nullptr,
        nullptr, nullptr, 0, 0, 0);

    // 5) softmax -> split att planes
    softmax512<<<128 * 512, 256>>>(att, ath, atl);

    // 6) o[b,h] = att @ hh_h
    gemm_p<0, 0, false><<<dim3(1, 4, BB * NHEAD), 256>>>(
        ath, atl, 512, (long)(4 * SNO), (long)SNO,
        hth, htl, 512, (long)SNO, (long)(128 * 512),
        nullptr, oh, ol, 512, (long)SNO, 128,
        512, NHEAD, nullptr, nullptr, nullptr, nullptr, nullptr,
        nullptr, nullptr, 0, 0, 0);

    // 7) conv1d(k=3,p=1) + bias + bn2 + relu -> out fp32
    gemm_p<1, 1, true><<<dim3(4, 4, BB), 256>>>(
        oh, ol, 512, (long)SNO, 0,
        cwh, cwl, 512, 0, 0,
        out, nullptr, nullptr, 512, (long)SNO, 0,
        3 * 512, 1, conv_b, bn2g, bn2b, bn2m, bn2v,
        nullptr, nullptr, 0, 0, 0);
}